// round 1
// baseline (speedup 1.0000x reference)
#include <cuda_runtime.h>
#include <math.h>

#define SEQ    4096
#define DMODEL 2048
#define NHEAD  16
#define DQK    128
#define DV     128

// Scratch (device globals: allocation-guard-safe)
__device__ float g_rq[NHEAD * SEQ * DQK];          // per-head q projection (then rope'd)
__device__ float g_rk[NHEAD * SEQ * DQK];          // per-head k projection (then rope'd)
__device__ float g_vs[NHEAD * SEQ * DV];           // per-head v projection
__device__ float g_z [SEQ * NHEAD * DV];           // attention out, layout [s][h*128+v]

#define NEG_INF (__int_as_float(0xff800000))

// ---------------------------------------------------------------------------
// Generic 128x128 SGEMM tile (BK=8, 256 threads, 8x8 microtile)
// ---------------------------------------------------------------------------
__device__ __forceinline__ void sgemm_tile(
    const float* __restrict__ A, int lda,
    const float* __restrict__ B, int ldb,
    float*       __restrict__ C, int ldc,
    int row0, int col0, int K, float scale)
{
    __shared__ float As[8][128];
    __shared__ float Bs[8][128];

    const int t  = threadIdx.x;
    const int tx = t & 15;
    const int ty = t >> 4;

    float acc[8][8];
#pragma unroll
    for (int i = 0; i < 8; i++)
#pragma unroll
        for (int j = 0; j < 8; j++) acc[i][j] = 0.0f;

    const int ra = t >> 1,  ca = (t & 1) * 4;   // A tile: 128 rows x 8 k
    const int rb = t >> 5,  cb = (t & 31) * 4;  // B tile: 8 k x 128 cols
    const float* Aptr = A + (row0 + ra) * (long)lda + ca;
    const float* Bptr = B + rb * (long)ldb + col0 + cb;

    for (int k0 = 0; k0 < K; k0 += 8) {
        float4 av = *(const float4*)(Aptr + k0);
        float4 bv = *(const float4*)(Bptr + (long)k0 * ldb);
        __syncthreads();
        As[ca + 0][ra] = av.x;
        As[ca + 1][ra] = av.y;
        As[ca + 2][ra] = av.z;
        As[ca + 3][ra] = av.w;
        *(float4*)&Bs[rb][cb] = bv;
        __syncthreads();
#pragma unroll
        for (int kk = 0; kk < 8; kk++) {
            float4 a0 = *(const float4*)&As[kk][ty * 8];
            float4 a1 = *(const float4*)&As[kk][ty * 8 + 4];
            float4 b0 = *(const float4*)&Bs[kk][tx * 8];
            float4 b1 = *(const float4*)&Bs[kk][tx * 8 + 4];
            float a[8] = {a0.x, a0.y, a0.z, a0.w, a1.x, a1.y, a1.z, a1.w};
            float b[8] = {b0.x, b0.y, b0.z, b0.w, b1.x, b1.y, b1.z, b1.w};
#pragma unroll
            for (int i = 0; i < 8; i++)
#pragma unroll
                for (int j = 0; j < 8; j++)
                    acc[i][j] = fmaf(a[i], b[j], acc[i][j]);
        }
    }

#pragma unroll
    for (int i = 0; i < 8; i++) {
        float* cp = C + (row0 + ty * 8 + i) * (long)ldc + col0 + tx * 8;
        float4 c0 = make_float4(acc[i][0] * scale, acc[i][1] * scale,
                                acc[i][2] * scale, acc[i][3] * scale);
        float4 c1 = make_float4(acc[i][4] * scale, acc[i][5] * scale,
                                acc[i][6] * scale, acc[i][7] * scale);
        *(float4*)cp       = c0;
        *(float4*)(cp + 4) = c1;
    }
}

// Projections: rq_raw/rk_raw/vs = x @ {q,k,v}[h]
__global__ void __launch_bounds__(256) proj_kernel(
    const float* __restrict__ x,
    const float* __restrict__ q,
    const float* __restrict__ k,
    const float* __restrict__ v)
{
    const int h = blockIdx.y;
    const int w = blockIdx.z;
    const float* W = (w == 0 ? q : (w == 1 ? k : v)) + (long)h * DMODEL * DQK;
    float*       C = (w == 0 ? g_rq : (w == 1 ? g_rk : g_vs)) + (long)h * SEQ * DQK;
    sgemm_tile(x, DMODEL, W, DQK, C, DQK, blockIdx.x * 128, 0, DMODEL, 1.0f);
}

// Output projection: out[s,d] = (1/2048) * sum_{h,v} z[s,h*128+v] * o[h,v,d]
__global__ void __launch_bounds__(256) outproj_kernel(
    const float* __restrict__ o, float* __restrict__ out)
{
    sgemm_tile(g_z, NHEAD * DV, o, DMODEL, out, DMODEL,
               blockIdx.x * 128, blockIdx.y * 128, NHEAD * DV, 4.8828125e-4f);
}

// ---------------------------------------------------------------------------
// RoPE (in place on g_rq / g_rk). Must reproduce jax bit patterns of rot:
// rate = theta * (-j/64) (exact fp32), rot = s * rate (single fp32 multiply).
// ---------------------------------------------------------------------------
__global__ void __launch_bounds__(256) rope_kernel(const float* __restrict__ theta)
{
    unsigned idx = blockIdx.x * 256u + threadIdx.x;     // 2 * 16 * 4096 * 64 = 2^23
    const float tf = theta[0];
    unsigned which = idx >> 22;
    unsigned rem   = idx & 4194303u;
    unsigned h     = rem >> 18;
    unsigned rem2  = rem & 262143u;
    unsigned s     = rem2 >> 6;
    unsigned j     = rem2 & 63u;

    float* P = (which ? g_rk : g_rq) + (long)h * (SEQ * DQK) + s * DQK + j;

    float rate = tf * (-(float)(int)j * 0.015625f);     // exact
    float rot  = __fmul_rn((float)(int)s, rate);        // matches jax's fp32 mul bitwise
    float sv, cv;
    sincosf(rot, &sv, &cv);                             // accurate full-range reduction

    float x1 = P[0];
    float x2 = P[64];
    // divide (not reciprocal-mul) to match jax's y / (128**0.25) rounding
    P[0]  = (cv * x1 - sv * x2) / 3.36358566101485845f;
    P[64] = (sv * x1 + cv * x2) / 3.36358566101485845f;
}

// ---------------------------------------------------------------------------
// Flash attention, fp32 SIMT. Block: 64 q-rows x one head. 256 threads.
// S tile 64x64 (4x4/thread), Z 64x128 (4 rows x 8 dims/thread).
// Shared: Rq[128][64] | union{Rk[128][64], Vs[64][128]} | Ps[64][64] = 80 KB.
// ---------------------------------------------------------------------------
__global__ void __launch_bounds__(256, 2) attn_kernel()
{
    extern __shared__ char smem[];
    float (*Rq)[64]  = (float(*)[64])(smem);
    float (*Rk)[64]  = (float(*)[64])(smem + 32768);
    float (*Vs)[128] = (float(*)[128])(smem + 32768);
    float (*Ps)[64]  = (float(*)[64])(smem + 65536);

    const int h  = blockIdx.y;
    const int qt = gridDim.x - 1 - blockIdx.x;   // heaviest (longest) tiles first
    const int r0 = qt * 64;
    const int t  = threadIdx.x;
    const int tx = t & 15;
    const int ty = t >> 4;

    const float* rqh = g_rq + (long)h * SEQ * DQK;
    const float* rkh = g_rk + (long)h * SEQ * DQK;
    const float* vsh = g_vs + (long)h * SEQ * DV;

    // Load Rq tile transposed: Rq[k][r]
    {
        int r = t >> 2, ko = (t & 3) * 32;
        const float* src = rqh + (long)(r0 + r) * DQK + ko;
#pragma unroll
        for (int u = 0; u < 8; u++) {
            float4 w = *(const float4*)(src + u * 4);
            Rq[ko + u * 4 + 0][r] = w.x;
            Rq[ko + u * 4 + 1][r] = w.y;
            Rq[ko + u * 4 + 2][r] = w.z;
            Rq[ko + u * 4 + 3][r] = w.w;
        }
    }

    float Z[4][8];
#pragma unroll
    for (int i = 0; i < 4; i++)
#pragma unroll
        for (int d = 0; d < 8; d++) Z[i][d] = 0.0f;
    float m[4], l[4];
#pragma unroll
    for (int i = 0; i < 4; i++) { m[i] = NEG_INF; l[i] = 0.0f; }

    const int ntiles = qt + 1;
    for (int tile = 0; tile < ntiles; tile++) {
        const int col0 = tile * 64;
        __syncthreads();   // previous PV finished with Ps/Vs; Rq visible (tile 0)

        // Load Rk tile transposed: Rk[k][c]
        {
            int r = t >> 2, ko = (t & 3) * 32;
            const float* src = rkh + (long)(col0 + r) * DQK + ko;
#pragma unroll
            for (int u = 0; u < 8; u++) {
                float4 w = *(const float4*)(src + u * 4);
                Rk[ko + u * 4 + 0][r] = w.x;
                Rk[ko + u * 4 + 1][r] = w.y;
                Rk[ko + u * 4 + 2][r] = w.z;
                Rk[ko + u * 4 + 3][r] = w.w;
            }
        }
        __syncthreads();

        // S = Rq_tile @ Rk_tile^T  (4x4 per thread)
        float s[4][4];
#pragma unroll
        for (int i = 0; i < 4; i++)
#pragma unroll
            for (int j = 0; j < 4; j++) s[i][j] = 0.0f;
#pragma unroll 8
        for (int kk = 0; kk < 128; kk++) {
            float4 a = *(const float4*)&Rq[kk][ty * 4];
            float4 b = *(const float4*)&Rk[kk][tx * 4];
            float av[4] = {a.x, a.y, a.z, a.w};
            float bv[4] = {b.x, b.y, b.z, b.w};
#pragma unroll
            for (int i = 0; i < 4; i++)
#pragma unroll
                for (int j = 0; j < 4; j++)
                    s[i][j] = fmaf(av[i], bv[j], s[i][j]);
        }

        // Causal mask (only the diagonal tile can contain masked entries)
        if (col0 == r0) {
#pragma unroll
            for (int i = 0; i < 4; i++)
#pragma unroll
                for (int j = 0; j < 4; j++)
                    if (col0 + tx * 4 + j > r0 + ty * 4 + i) s[i][j] = NEG_INF;
        }

        // Online softmax update (row group = 16 consecutive lanes)
        float alpha[4];
#pragma unroll
        for (int i = 0; i < 4; i++) {
            float tmax = fmaxf(fmaxf(s[i][0], s[i][1]), fmaxf(s[i][2], s[i][3]));
            for (int off = 8; off; off >>= 1)
                tmax = fmaxf(tmax, __shfl_xor_sync(0xffffffffu, tmax, off));
            float mn = fmaxf(m[i], tmax);
            alpha[i] = expf(m[i] - mn);
            m[i] = mn;
            float rs = 0.0f;
#pragma unroll
            for (int j = 0; j < 4; j++) {
                s[i][j] = expf(s[i][j] - mn);
                rs += s[i][j];
            }
            for (int off = 8; off; off >>= 1)
                rs += __shfl_xor_sync(0xffffffffu, rs, off);
            l[i] = l[i] * alpha[i] + rs;
#pragma unroll
            for (int d = 0; d < 8; d++) Z[i][d] *= alpha[i];
        }

        __syncthreads();   // everyone done reading Rk

        // Store P tile; load V tile (reuses Rk buffer)
#pragma unroll
        for (int i = 0; i < 4; i++)
            *(float4*)&Ps[ty * 4 + i][tx * 4] =
                make_float4(s[i][0], s[i][1], s[i][2], s[i][3]);
        {
            int c = t >> 2, ko = (t & 3) * 32;
            const float* src = vsh + (long)(col0 + c) * DV + ko;
#pragma unroll
            for (int u = 0; u < 8; u++)
                *(float4*)&Vs[c][ko + u * 4] = *(const float4*)(src + u * 4);
        }
        __syncthreads();

        // Z += P @ V_tile
#pragma unroll 4
        for (int c4 = 0; c4 < 16; c4++) {
            float4 pv[4];
#pragma unroll
            for (int i = 0; i < 4; i++)
                pv[i] = *(const float4*)&Ps[ty * 4 + i][c4 * 4];
#pragma unroll
            for (int cc = 0; cc < 4; cc++) {
                float4 v0 = *(const float4*)&Vs[c4 * 4 + cc][tx * 8];
                float4 v1 = *(const float4*)&Vs[c4 * 4 + cc][tx * 8 + 4];
                float vv[8] = {v0.x, v0.y, v0.z, v0.w, v1.x, v1.y, v1.z, v1.w};
#pragma unroll
                for (int i = 0; i < 4; i++) {
                    float pw = (cc == 0 ? pv[i].x : cc == 1 ? pv[i].y
                                : cc == 2 ? pv[i].z : pv[i].w);
#pragma unroll
                    for (int d = 0; d < 8; d++)
                        Z[i][d] = fmaf(pw, vv[d], Z[i][d]);
                }
            }
        }
    }

    // Normalize and write z as [s][h*128+v]
#pragma unroll
    for (int i = 0; i < 4; i++) {
        float invl = 1.0f / l[i];
        float* dst = g_z + (long)(r0 + ty * 4 + i) * (NHEAD * DV) + h * DV + tx * 8;
        *(float4*)dst =
            make_float4(Z[i][0] * invl, Z[i][1] * invl, Z[i][2] * invl, Z[i][3] * invl);
        *(float4*)(dst + 4) =
            make_float4(Z[i][4] * invl, Z[i][5] * invl, Z[i][6] * invl, Z[i][7] * invl);
    }
}

// ---------------------------------------------------------------------------
extern "C" void kernel_launch(void* const* d_in, const int* in_sizes, int n_in,
                              void* d_out, int out_size)
{
    const float* x     = (const float*)d_in[0];
    const float* q     = (const float*)d_in[1];
    const float* k     = (const float*)d_in[2];
    const float* v     = (const float*)d_in[3];
    const float* o     = (const float*)d_in[4];
    const float* theta = (const float*)d_in[5];
    float* out = (float*)d_out;

    cudaFuncSetAttribute(attn_kernel,
                         cudaFuncAttributeMaxDynamicSharedMemorySize, 81920);

    proj_kernel<<<dim3(32, 16, 3), 256>>>(x, q, k, v);
    rope_kernel<<<32768, 256>>>(theta);
    attn_kernel<<<dim3(64, 16), 256, 81920>>>();
    outproj_kernel<<<dim3(32, 16), 256>>>(o, out);
}

// round 2
// speedup vs baseline: 1.0028x; 1.0028x over previous
#include <cuda_runtime.h>
#include <math.h>

#define SEQ    4096
#define DMODEL 2048
#define NHEAD  16
#define DQK    128
#define DV     128

// Scratch (device globals: allocation-guard-safe)
__device__ float g_rq[NHEAD * SEQ * DQK];          // per-head q projection (then rope'd)
__device__ float g_rk[NHEAD * SEQ * DQK];          // per-head k projection (then rope'd)
__device__ float g_vs[NHEAD * SEQ * DV];           // per-head v projection
__device__ float g_z [SEQ * NHEAD * DV];           // attention out, layout [s][h*128+v]

#define NEG_INF (__int_as_float(0xff800000))

// ---------------------------------------------------------------------------
// Generic 128x128 SGEMM tile (BK=8, 256 threads, 8x8 microtile)
// ---------------------------------------------------------------------------
__device__ __forceinline__ void sgemm_tile(
    const float* __restrict__ A, int lda,
    const float* __restrict__ B, int ldb,
    float*       __restrict__ C, int ldc,
    int row0, int col0, int K, float scale)
{
    __shared__ float As[8][128];
    __shared__ float Bs[8][128];

    const int t  = threadIdx.x;
    const int tx = t & 15;
    const int ty = t >> 4;

    float acc[8][8];
#pragma unroll
    for (int i = 0; i < 8; i++)
#pragma unroll
        for (int j = 0; j < 8; j++) acc[i][j] = 0.0f;

    const int ra = t >> 1,  ca = (t & 1) * 4;   // A tile: 128 rows x 8 k
    const int rb = t >> 5,  cb = (t & 31) * 4;  // B tile: 8 k x 128 cols
    const float* Aptr = A + (row0 + ra) * (long)lda + ca;
    const float* Bptr = B + rb * (long)ldb + col0 + cb;

    for (int k0 = 0; k0 < K; k0 += 8) {
        float4 av = *(const float4*)(Aptr + k0);
        float4 bv = *(const float4*)(Bptr + (long)k0 * ldb);
        __syncthreads();
        As[ca + 0][ra] = av.x;
        As[ca + 1][ra] = av.y;
        As[ca + 2][ra] = av.z;
        As[ca + 3][ra] = av.w;
        *(float4*)&Bs[rb][cb] = bv;
        __syncthreads();
#pragma unroll
        for (int kk = 0; kk < 8; kk++) {
            float4 a0 = *(const float4*)&As[kk][ty * 8];
            float4 a1 = *(const float4*)&As[kk][ty * 8 + 4];
            float4 b0 = *(const float4*)&Bs[kk][tx * 8];
            float4 b1 = *(const float4*)&Bs[kk][tx * 8 + 4];
            float a[8] = {a0.x, a0.y, a0.z, a0.w, a1.x, a1.y, a1.z, a1.w};
            float b[8] = {b0.x, b0.y, b0.z, b0.w, b1.x, b1.y, b1.z, b1.w};
#pragma unroll
            for (int i = 0; i < 8; i++)
#pragma unroll
                for (int j = 0; j < 8; j++)
                    acc[i][j] = fmaf(a[i], b[j], acc[i][j]);
        }
    }

#pragma unroll
    for (int i = 0; i < 8; i++) {
        float* cp = C + (row0 + ty * 8 + i) * (long)ldc + col0 + tx * 8;
        float4 c0 = make_float4(acc[i][0] * scale, acc[i][1] * scale,
                                acc[i][2] * scale, acc[i][3] * scale);
        float4 c1 = make_float4(acc[i][4] * scale, acc[i][5] * scale,
                                acc[i][6] * scale, acc[i][7] * scale);
        *(float4*)cp       = c0;
        *(float4*)(cp + 4) = c1;
    }
}

// Projections: rq_raw/rk_raw/vs = x @ {q,k,v}[h]
__global__ void __launch_bounds__(256) proj_kernel(
    const float* __restrict__ x,
    const float* __restrict__ q,
    const float* __restrict__ k,
    const float* __restrict__ v)
{
    const int h = blockIdx.y;
    const int w = blockIdx.z;
    const float* W = (w == 0 ? q : (w == 1 ? k : v)) + (long)h * DMODEL * DQK;
    float*       C = (w == 0 ? g_rq : (w == 1 ? g_rk : g_vs)) + (long)h * SEQ * DQK;
    sgemm_tile(x, DMODEL, W, DQK, C, DQK, blockIdx.x * 128, 0, DMODEL, 1.0f);
}

// Output projection: out[s,d] = (1/2048) * sum_{h,v} z[s,h*128+v] * o[h,v,d]
__global__ void __launch_bounds__(256) outproj_kernel(
    const float* __restrict__ o, float* __restrict__ out)
{
    sgemm_tile(g_z, NHEAD * DV, o, DMODEL, out, DMODEL,
               blockIdx.x * 128, blockIdx.y * 128, NHEAD * DV, 4.8828125e-4f);
}

// ---------------------------------------------------------------------------
// RoPE (in place on g_rq / g_rk). Must reproduce jax bit patterns of rot:
// rate = theta * (-j/64) (exact fp32), rot = s * rate (single fp32 multiply).
// ---------------------------------------------------------------------------
__global__ void __launch_bounds__(256) rope_kernel(const float* __restrict__ theta)
{
    unsigned idx = blockIdx.x * 256u + threadIdx.x;     // 2 * 16 * 4096 * 64 = 2^23
    const float tf = theta[0];
    unsigned which = idx >> 22;
    unsigned rem   = idx & 4194303u;
    unsigned h     = rem >> 18;
    unsigned rem2  = rem & 262143u;
    unsigned s     = rem2 >> 6;
    unsigned j     = rem2 & 63u;

    float* P = (which ? g_rk : g_rq) + (long)h * (SEQ * DQK) + s * DQK + j;

    float rate = tf * (-(float)(int)j * 0.015625f);     // exact
    float rot  = __fmul_rn((float)(int)s, rate);        // matches jax's fp32 mul bitwise
    float sv, cv;
    sincosf(rot, &sv, &cv);                             // accurate full-range reduction

    float x1 = P[0];
    float x2 = P[64];
    // divide (not reciprocal-mul) to match jax's y / (128**0.25) rounding
    P[0]  = (cv * x1 - sv * x2) / 3.36358566101485845f;
    P[64] = (sv * x1 + cv * x2) / 3.36358566101485845f;
}

// ---------------------------------------------------------------------------
// Flash attention, fp32 SIMT. Block: 64 q-rows x one head. 256 threads.
// S tile 64x64 (4x4/thread), Z 64x128 (4 rows x 8 dims/thread).
// Shared: Rq[128][64] | union{Rk[128][64], Vs[64][128]} | Ps[64][64] = 80 KB.
// ---------------------------------------------------------------------------
__global__ void __launch_bounds__(256, 2) attn_kernel()
{
    extern __shared__ char smem[];
    float (*Rq)[64]  = (float(*)[64])(smem);
    float (*Rk)[64]  = (float(*)[64])(smem + 32768);
    float (*Vs)[128] = (float(*)[128])(smem + 32768);
    float (*Ps)[64]  = (float(*)[64])(smem + 65536);

    const int h  = blockIdx.y;
    const int qt = gridDim.x - 1 - blockIdx.x;   // heaviest (longest) tiles first
    const int r0 = qt * 64;
    const int t  = threadIdx.x;
    const int tx = t & 15;
    const int ty = t >> 4;

    const float* rqh = g_rq + (long)h * SEQ * DQK;
    const float* rkh = g_rk + (long)h * SEQ * DQK;
    const float* vsh = g_vs + (long)h * SEQ * DV;

    // Load Rq tile transposed: Rq[k][r]
    {
        int r = t >> 2, ko = (t & 3) * 32;
        const float* src = rqh + (long)(r0 + r) * DQK + ko;
#pragma unroll
        for (int u = 0; u < 8; u++) {
            float4 w = *(const float4*)(src + u * 4);
            Rq[ko + u * 4 + 0][r] = w.x;
            Rq[ko + u * 4 + 1][r] = w.y;
            Rq[ko + u * 4 + 2][r] = w.z;
            Rq[ko + u * 4 + 3][r] = w.w;
        }
    }

    float Z[4][8];
#pragma unroll
    for (int i = 0; i < 4; i++)
#pragma unroll
        for (int d = 0; d < 8; d++) Z[i][d] = 0.0f;
    float m[4], l[4];
#pragma unroll
    for (int i = 0; i < 4; i++) { m[i] = NEG_INF; l[i] = 0.0f; }

    const int ntiles = qt + 1;
    for (int tile = 0; tile < ntiles; tile++) {
        const int col0 = tile * 64;
        __syncthreads();   // previous PV finished with Ps/Vs; Rq visible (tile 0)

        // Load Rk tile transposed: Rk[k][c]
        {
            int r = t >> 2, ko = (t & 3) * 32;
            const float* src = rkh + (long)(col0 + r) * DQK + ko;
#pragma unroll
            for (int u = 0; u < 8; u++) {
                float4 w = *(const float4*)(src + u * 4);
                Rk[ko + u * 4 + 0][r] = w.x;
                Rk[ko + u * 4 + 1][r] = w.y;
                Rk[ko + u * 4 + 2][r] = w.z;
                Rk[ko + u * 4 + 3][r] = w.w;
            }
        }
        __syncthreads();

        // S = Rq_tile @ Rk_tile^T  (4x4 per thread)
        float s[4][4];
#pragma unroll
        for (int i = 0; i < 4; i++)
#pragma unroll
            for (int j = 0; j < 4; j++) s[i][j] = 0.0f;
#pragma unroll 8
        for (int kk = 0; kk < 128; kk++) {
            float4 a = *(const float4*)&Rq[kk][ty * 4];
            float4 b = *(const float4*)&Rk[kk][tx * 4];
            float av[4] = {a.x, a.y, a.z, a.w};
            float bv[4] = {b.x, b.y, b.z, b.w};
#pragma unroll
            for (int i = 0; i < 4; i++)
#pragma unroll
                for (int j = 0; j < 4; j++)
                    s[i][j] = fmaf(av[i], bv[j], s[i][j]);
        }

        // Causal mask (only the diagonal tile can contain masked entries)
        if (col0 == r0) {
#pragma unroll
            for (int i = 0; i < 4; i++)
#pragma unroll
                for (int j = 0; j < 4; j++)
                    if (col0 + tx * 4 + j > r0 + ty * 4 + i) s[i][j] = NEG_INF;
        }

        // Online softmax update (row group = 16 consecutive lanes)
        float alpha[4];
#pragma unroll
        for (int i = 0; i < 4; i++) {
            float tmax = fmaxf(fmaxf(s[i][0], s[i][1]), fmaxf(s[i][2], s[i][3]));
            for (int off = 8; off; off >>= 1)
                tmax = fmaxf(tmax, __shfl_xor_sync(0xffffffffu, tmax, off));
            float mn = fmaxf(m[i], tmax);
            alpha[i] = expf(m[i] - mn);
            m[i] = mn;
            float rs = 0.0f;
#pragma unroll
            for (int j = 0; j < 4; j++) {
                s[i][j] = expf(s[i][j] - mn);
                rs += s[i][j];
            }
            for (int off = 8; off; off >>= 1)
                rs += __shfl_xor_sync(0xffffffffu, rs, off);
            l[i] = l[i] * alpha[i] + rs;
#pragma unroll
            for (int d = 0; d < 8; d++) Z[i][d] *= alpha[i];
        }

        __syncthreads();   // everyone done reading Rk

        // Store P tile; load V tile (reuses Rk buffer)
#pragma unroll
        for (int i = 0; i < 4; i++)
            *(float4*)&Ps[ty * 4 + i][tx * 4] =
                make_float4(s[i][0], s[i][1], s[i][2], s[i][3]);
        {
            int c = t >> 2, ko = (t & 3) * 32;
            const float* src = vsh + (long)(col0 + c) * DV + ko;
#pragma unroll
            for (int u = 0; u < 8; u++)
                *(float4*)&Vs[c][ko + u * 4] = *(const float4*)(src + u * 4);
        }
        __syncthreads();

        // Z += P @ V_tile
#pragma unroll 4
        for (int c4 = 0; c4 < 16; c4++) {
            float4 pv[4];
#pragma unroll
            for (int i = 0; i < 4; i++)
                pv[i] = *(const float4*)&Ps[ty * 4 + i][c4 * 4];
#pragma unroll
            for (int cc = 0; cc < 4; cc++) {
                float4 v0 = *(const float4*)&Vs[c4 * 4 + cc][tx * 8];
                float4 v1 = *(const float4*)&Vs[c4 * 4 + cc][tx * 8 + 4];
                float vv[8] = {v0.x, v0.y, v0.z, v0.w, v1.x, v1.y, v1.z, v1.w};
#pragma unroll
                for (int i = 0; i < 4; i++) {
                    float pw = (cc == 0 ? pv[i].x : cc == 1 ? pv[i].y
                                : cc == 2 ? pv[i].z : pv[i].w);
#pragma unroll
                    for (int d = 0; d < 8; d++)
                        Z[i][d] = fmaf(pw, vv[d], Z[i][d]);
                }
            }
        }
    }

    // Normalize and write z as [s][h*128+v]
#pragma unroll
    for (int i = 0; i < 4; i++) {
        float invl = 1.0f / l[i];
        float* dst = g_z + (long)(r0 + ty * 4 + i) * (NHEAD * DV) + h * DV + tx * 8;
        *(float4*)dst =
            make_float4(Z[i][0] * invl, Z[i][1] * invl, Z[i][2] * invl, Z[i][3] * invl);
        *(float4*)(dst + 4) =
            make_float4(Z[i][4] * invl, Z[i][5] * invl, Z[i][6] * invl, Z[i][7] * invl);
    }
}

// ---------------------------------------------------------------------------
extern "C" void kernel_launch(void* const* d_in, const int* in_sizes, int n_in,
                              void* d_out, int out_size)
{
    const float* x     = (const float*)d_in[0];
    const float* q     = (const float*)d_in[1];
    const float* k     = (const float*)d_in[2];
    const float* v     = (const float*)d_in[3];
    const float* o     = (const float*)d_in[4];
    const float* theta = (const float*)d_in[5];
    float* out = (float*)d_out;

    cudaFuncSetAttribute(attn_kernel,
                         cudaFuncAttributeMaxDynamicSharedMemorySize, 81920);

    proj_kernel<<<dim3(32, 16, 3), 256>>>(x, q, k, v);
    rope_kernel<<<32768, 256>>>(theta);
    attn_kernel<<<dim3(64, 16), 256, 81920>>>();
    outproj_kernel<<<dim3(32, 16), 256>>>(o, out);
}

// round 6
// speedup vs baseline: 1.1954x; 1.1921x over previous
#include <cuda_runtime.h>
#include <cuda_bf16.h>
#include <math.h>
#include <stdint.h>

#define SEQ    4096
#define DM     2048
#define NHEAD  16
#define DQK    128
#define DV     128

typedef __nv_bfloat16 bf16;

// ---------------- scratch: 128 MiB total, same as passing R1 ----------------
__device__ float g_pq[NHEAD * SEQ * DQK];
__device__ float g_pk[NHEAD * SEQ * DQK];
__device__ float g_pv[NHEAD * SEQ * DQK];
__device__ float g_z [SEQ * NHEAD * DV];           // [s][h*128+v]

#define NEG_INF (__int_as_float(0xff800000))

// ---------------- HMMA helpers ---------------------------------------------
__device__ __forceinline__ void mma16816(float* c, const uint32_t* a, const uint32_t* b) {
    asm volatile(
        "mma.sync.aligned.m16n8k16.row.col.f32.bf16.bf16.f32 "
        "{%0,%1,%2,%3}, {%4,%5,%6,%7}, {%8,%9}, {%0,%1,%2,%3};"
        : "+f"(c[0]), "+f"(c[1]), "+f"(c[2]), "+f"(c[3])
        : "r"(a[0]), "r"(a[1]), "r"(a[2]), "r"(a[3]), "r"(b[0]), "r"(b[1]));
}

// pack two fp32 into bf16x2 hi word + bf16x2 lo word (v0 -> low half)
__device__ __forceinline__ uint32_t pack_split(float a, float b, uint32_t& lopk) {
    bf16 ha = __float2bfloat16(a), hb = __float2bfloat16(b);
    bf16 la = __float2bfloat16(a - __bfloat162float(ha));
    bf16 lb = __float2bfloat16(b - __bfloat162float(hb));
    lopk = (uint32_t)__bfloat16_as_ushort(la) |
           ((uint32_t)__bfloat16_as_ushort(lb) << 16);
    return (uint32_t)__bfloat16_as_ushort(ha) |
           ((uint32_t)__bfloat16_as_ushort(hb) << 16);
}

// ---------------------------------------------------------------------------
// Split-bf16 HMMA GEMM, fp32 in / fp32 out, split+transpose fused in loader.
//   C[128,128] = A[128,2048] @ B[2048,128]        (B given [k][n], n contig)
// 8 warps (2m x 4n), warp tile 64x32, k-chunk 32, static smem (43KB).
// smem tiles: [128 rows][16 u32 = 32 halves] pitch 21 u32 (bank-safe).
// ---------------------------------------------------------------------------
#define PIT 21

__device__ __forceinline__ void gemm128f(
    const float* __restrict__ A, int lda,
    const float* __restrict__ B, int ldb,
    float* __restrict__ C, int ldc, float scale)
{
    __shared__ uint32_t sAh[128 * PIT], sAl[128 * PIT];
    __shared__ uint32_t sBh[128 * PIT], sBl[128 * PIT];

    const int t = threadIdx.x, lane = t & 31, wid = t >> 5;
    const int wm = (wid >> 2) * 64, wn = (wid & 3) * 32;
    const int g = lane >> 2, qq = lane & 3;

    // loader mapping
    const int arow = t >> 1,  aseg = t & 1;        // A: 128 rows x 2 segs of 16 floats
    const int bkp  = t >> 4,  bnc  = (t & 15) * 8; // B: 16 k-pairs x 16 n-groups of 8

    const float* pA  = A + (size_t)arow * lda + aseg * 16;
    const float* pB0 = B + (size_t)(2 * bkp) * ldb + bnc;
    const float* pB1 = pB0 + ldb;

    float acc[4][4][4];
#pragma unroll
    for (int i = 0; i < 4; i++)
#pragma unroll
        for (int j = 0; j < 4; j++)
#pragma unroll
            for (int r = 0; r < 4; r++) acc[i][j][r] = 0.0f;

    float a_f[16], b_f[16];
    // prefetch chunk 0
#pragma unroll
    for (int u = 0; u < 4; u++) {
        float4 v = *(const float4*)(pA + u * 4);
        a_f[u*4+0] = v.x; a_f[u*4+1] = v.y; a_f[u*4+2] = v.z; a_f[u*4+3] = v.w;
    }
#pragma unroll
    for (int u = 0; u < 2; u++) {
        float4 v0 = *(const float4*)(pB0 + u * 4);
        float4 v1 = *(const float4*)(pB1 + u * 4);
        b_f[u*4+0] = v0.x; b_f[u*4+1] = v0.y; b_f[u*4+2] = v0.z; b_f[u*4+3] = v0.w;
        b_f[8+u*4+0] = v1.x; b_f[8+u*4+1] = v1.y; b_f[8+u*4+2] = v1.z; b_f[8+u*4+3] = v1.w;
    }

    for (int kc = 0; kc < 64; kc++) {
        __syncthreads();   // previous compute done reading smem
        // store split tiles
#pragma unroll
        for (int u2 = 0; u2 < 8; u2++) {
            uint32_t lo, hi = pack_split(a_f[2*u2], a_f[2*u2+1], lo);
            sAh[arow * PIT + aseg * 8 + u2] = hi;
            sAl[arow * PIT + aseg * 8 + u2] = lo;
        }
#pragma unroll
        for (int n = 0; n < 8; n++) {
            uint32_t lo, hi = pack_split(b_f[n], b_f[8 + n], lo);
            sBh[(bnc + n) * PIT + bkp] = hi;
            sBl[(bnc + n) * PIT + bkp] = lo;
        }
        // prefetch next chunk
        if (kc < 63) {
            const size_t ao = (size_t)(kc + 1) * 32;
            const size_t bo = (size_t)(kc + 1) * 32 * ldb;
#pragma unroll
            for (int u = 0; u < 4; u++) {
                float4 v = *(const float4*)(pA + ao + u * 4);
                a_f[u*4+0] = v.x; a_f[u*4+1] = v.y; a_f[u*4+2] = v.z; a_f[u*4+3] = v.w;
            }
#pragma unroll
            for (int u = 0; u < 2; u++) {
                float4 v0 = *(const float4*)(pB0 + bo + u * 4);
                float4 v1 = *(const float4*)(pB1 + bo + u * 4);
                b_f[u*4+0] = v0.x; b_f[u*4+1] = v0.y; b_f[u*4+2] = v0.z; b_f[u*4+3] = v0.w;
                b_f[8+u*4+0] = v1.x; b_f[8+u*4+1] = v1.y; b_f[8+u*4+2] = v1.z; b_f[8+u*4+3] = v1.w;
            }
        }
        __syncthreads();   // smem tiles ready

#pragma unroll
        for (int ks = 0; ks < 2; ks++) {
            uint32_t a_h[4][4], a_l[4][4];
#pragma unroll
            for (int i = 0; i < 4; i++) {
                const int w0 = (wm + i * 16 + g) * PIT + ks * 8 + qq;
                a_h[i][0] = sAh[w0];
                a_h[i][1] = sAh[w0 + 8 * PIT];
                a_h[i][2] = sAh[w0 + 4];
                a_h[i][3] = sAh[w0 + 8 * PIT + 4];
                a_l[i][0] = sAl[w0];
                a_l[i][1] = sAl[w0 + 8 * PIT];
                a_l[i][2] = sAl[w0 + 4];
                a_l[i][3] = sAl[w0 + 8 * PIT + 4];
            }
#pragma unroll
            for (int j = 0; j < 4; j++) {
                const int w0 = (wn + j * 8 + g) * PIT + ks * 8 + qq;
                uint32_t bh[2] = { sBh[w0], sBh[w0 + 4] };
                uint32_t bl[2] = { sBl[w0], sBl[w0 + 4] };
#pragma unroll
                for (int i = 0; i < 4; i++) {
                    mma16816(acc[i][j], a_h[i], bh);
                    mma16816(acc[i][j], a_l[i], bh);
                    mma16816(acc[i][j], a_h[i], bl);
                }
            }
        }
    }

#pragma unroll
    for (int i = 0; i < 4; i++)
#pragma unroll
        for (int j = 0; j < 4; j++) {
            const int row = wm + i * 16 + g;
            const int col = wn + j * 8 + qq * 2;
            float2 lo = make_float2(acc[i][j][0] * scale, acc[i][j][1] * scale);
            float2 hi = make_float2(acc[i][j][2] * scale, acc[i][j][3] * scale);
            *(float2*)(C + (size_t)row * ldc + col)       = lo;
            *(float2*)(C + (size_t)(row + 8) * ldc + col) = hi;
        }
}

// Projections: pq/pk/pv[h] = x @ W[h]   (W is [DM][DQK], n-contiguous)
__global__ void __launch_bounds__(256) proj_hmma(
    const float* __restrict__ x,
    const float* __restrict__ q,
    const float* __restrict__ k,
    const float* __restrict__ v)
{
    const int h = blockIdx.y, w = blockIdx.z;
    const float* W = (w == 0 ? q : (w == 1 ? k : v)) + (size_t)h * DM * DQK;
    float* C = (w == 0 ? g_pq : w == 1 ? g_pk : g_pv) +
               (size_t)h * SEQ * DQK + (size_t)blockIdx.x * 128 * DQK;
    gemm128f(x + (size_t)blockIdx.x * 128 * DM, DM, W, DQK, C, DQK, 1.0f);
}

// out[s,d] = (1/2048) * sum_hv z[s,hv] * o[hv,d]   (o flattened [2048][2048])
__global__ void __launch_bounds__(256) outproj_hmma(
    const float* __restrict__ o, float* __restrict__ out)
{
    gemm128f(g_z + (size_t)blockIdx.x * 128 * 2048, 2048,
             o + blockIdx.y * 128, 2048,
             out + (size_t)blockIdx.x * 128 * DM + blockIdx.y * 128,
             DM, 4.8828125e-4f);
}

// ---------------------------------------------------------------------------
// RoPE in place on g_pq / g_pk (bit-exact vs jax; proven in R1)
// ---------------------------------------------------------------------------
__global__ void __launch_bounds__(256) rope_kernel(const float* __restrict__ theta)
{
    unsigned idx = blockIdx.x * 256u + threadIdx.x;     // 2^23
    const float tf = theta[0];
    unsigned which = idx >> 22;
    unsigned rem   = idx & 4194303u;
    unsigned h     = rem >> 18;
    unsigned rem2  = rem & 262143u;
    unsigned s     = rem2 >> 6;
    unsigned j     = rem2 & 63u;

    float* P = (which ? g_pk : g_pq) + (size_t)h * (SEQ * DQK) + s * DQK + j;

    float rate = tf * (-(float)(int)j * 0.015625f);
    float rot  = __fmul_rn((float)(int)s, rate);
    float sv, cv;
    sincosf(rot, &sv, &cv);

    float x1 = P[0];
    float x2 = P[64];
    P[0]  = (cv * x1 - sv * x2) / 3.36358566101485845f;
    P[64] = (sv * x1 + cv * x2) / 3.36358566101485845f;
}

// ---------------------------------------------------------------------------
// Flash attention, fp32 SIMT (R1, proven). 64 q-rows x one head, 256 threads.
// ---------------------------------------------------------------------------
__global__ void __launch_bounds__(256, 2) attn_kernel()
{
    extern __shared__ char smem[];
    float (*Rq)[64]  = (float(*)[64])(smem);
    float (*Rk)[64]  = (float(*)[64])(smem + 32768);
    float (*Vs)[128] = (float(*)[128])(smem + 32768);
    float (*Ps)[64]  = (float(*)[64])(smem + 65536);

    const int h  = blockIdx.y;
    const int qt = gridDim.x - 1 - blockIdx.x;
    const int r0 = qt * 64;
    const int t  = threadIdx.x;
    const int tx = t & 15;
    const int ty = t >> 4;

    const float* rqh = g_pq + (size_t)h * SEQ * DQK;
    const float* rkh = g_pk + (size_t)h * SEQ * DQK;
    const float* vsh = g_pv + (size_t)h * SEQ * DV;

    {
        int r = t >> 2, ko = (t & 3) * 32;
        const float* src = rqh + (size_t)(r0 + r) * DQK + ko;
#pragma unroll
        for (int u = 0; u < 8; u++) {
            float4 w = *(const float4*)(src + u * 4);
            Rq[ko + u * 4 + 0][r] = w.x;
            Rq[ko + u * 4 + 1][r] = w.y;
            Rq[ko + u * 4 + 2][r] = w.z;
            Rq[ko + u * 4 + 3][r] = w.w;
        }
    }

    float Z[4][8];
#pragma unroll
    for (int i = 0; i < 4; i++)
#pragma unroll
        for (int d = 0; d < 8; d++) Z[i][d] = 0.0f;
    float m[4], l[4];
#pragma unroll
    for (int i = 0; i < 4; i++) { m[i] = NEG_INF; l[i] = 0.0f; }

    const int ntiles = qt + 1;
    for (int tile = 0; tile < ntiles; tile++) {
        const int col0 = tile * 64;
        __syncthreads();

        {
            int r = t >> 2, ko = (t & 3) * 32;
            const float* src = rkh + (size_t)(col0 + r) * DQK + ko;
#pragma unroll
            for (int u = 0; u < 8; u++) {
                float4 w = *(const float4*)(src + u * 4);
                Rk[ko + u * 4 + 0][r] = w.x;
                Rk[ko + u * 4 + 1][r] = w.y;
                Rk[ko + u * 4 + 2][r] = w.z;
                Rk[ko + u * 4 + 3][r] = w.w;
            }
        }
        __syncthreads();

        float s[4][4];
#pragma unroll
        for (int i = 0; i < 4; i++)
#pragma unroll
            for (int j = 0; j < 4; j++) s[i][j] = 0.0f;
#pragma unroll 8
        for (int kk = 0; kk < 128; kk++) {
            float4 a = *(const float4*)&Rq[kk][ty * 4];
            float4 b = *(const float4*)&Rk[kk][tx * 4];
            float av[4] = {a.x, a.y, a.z, a.w};
            float bv[4] = {b.x, b.y, b.z, b.w};
#pragma unroll
            for (int i = 0; i < 4; i++)
#pragma unroll
                for (int j = 0; j < 4; j++)
                    s[i][j] = fmaf(av[i], bv[j], s[i][j]);
        }

        if (col0 == r0) {
#pragma unroll
            for (int i = 0; i < 4; i++)
#pragma unroll
                for (int j = 0; j < 4; j++)
                    if (col0 + tx * 4 + j > r0 + ty * 4 + i) s[i][j] = NEG_INF;
        }

        float alpha[4];
#pragma unroll
        for (int i = 0; i < 4; i++) {
            float tmax = fmaxf(fmaxf(s[i][0], s[i][1]), fmaxf(s[i][2], s[i][3]));
            for (int off = 8; off; off >>= 1)
                tmax = fmaxf(tmax, __shfl_xor_sync(0xffffffffu, tmax, off));
            float mn = fmaxf(m[i], tmax);
            alpha[i] = expf(m[i] - mn);
            m[i] = mn;
            float rs = 0.0f;
#pragma unroll
            for (int j = 0; j < 4; j++) {
                s[i][j] = expf(s[i][j] - mn);
                rs += s[i][j];
            }
            for (int off = 8; off; off >>= 1)
                rs += __shfl_xor_sync(0xffffffffu, rs, off);
            l[i] = l[i] * alpha[i] + rs;
#pragma unroll
            for (int d = 0; d < 8; d++) Z[i][d] *= alpha[i];
        }

        __syncthreads();

#pragma unroll
        for (int i = 0; i < 4; i++)
            *(float4*)&Ps[ty * 4 + i][tx * 4] =
                make_float4(s[i][0], s[i][1], s[i][2], s[i][3]);
        {
            int c = t >> 2, ko = (t & 3) * 32;
            const float* src = vsh + (size_t)(col0 + c) * DV + ko;
#pragma unroll
            for (int u = 0; u < 8; u++)
                *(float4*)&Vs[c][ko + u * 4] = *(const float4*)(src + u * 4);
        }
        __syncthreads();

#pragma unroll 4
        for (int c4 = 0; c4 < 16; c4++) {
            float4 pv[4];
#pragma unroll
            for (int i = 0; i < 4; i++)
                pv[i] = *(const float4*)&Ps[ty * 4 + i][c4 * 4];
#pragma unroll
            for (int cc = 0; cc < 4; cc++) {
                float4 v0 = *(const float4*)&Vs[c4 * 4 + cc][tx * 8];
                float4 v1 = *(const float4*)&Vs[c4 * 4 + cc][tx * 8 + 4];
                float vv[8] = {v0.x, v0.y, v0.z, v0.w, v1.x, v1.y, v1.z, v1.w};
#pragma unroll
                for (int i = 0; i < 4; i++) {
                    float pw = (cc == 0 ? pv[i].x : cc == 1 ? pv[i].y
                                : cc == 2 ? pv[i].z : pv[i].w);
#pragma unroll
                    for (int d = 0; d < 8; d++)
                        Z[i][d] = fmaf(pw, vv[d], Z[i][d]);
                }
            }
        }
    }

#pragma unroll
    for (int i = 0; i < 4; i++) {
        float invl = 1.0f / l[i];
        float* dst = g_z + (size_t)(r0 + ty * 4 + i) * (NHEAD * DV) + h * DV + tx * 8;
        *(float4*)dst =
            make_float4(Z[i][0] * invl, Z[i][1] * invl, Z[i][2] * invl, Z[i][3] * invl);
        *(float4*)(dst + 4) =
            make_float4(Z[i][4] * invl, Z[i][5] * invl, Z[i][6] * invl, Z[i][7] * invl);
    }
}

// ---------------------------------------------------------------------------
extern "C" void kernel_launch(void* const* d_in, const int* in_sizes, int n_in,
                              void* d_out, int out_size)
{
    const float* x     = (const float*)d_in[0];
    const float* q     = (const float*)d_in[1];
    const float* k     = (const float*)d_in[2];
    const float* v     = (const float*)d_in[3];
    const float* o     = (const float*)d_in[4];
    const float* theta = (const float*)d_in[5];
    float* out = (float*)d_out;

    cudaFuncSetAttribute(attn_kernel,
                         cudaFuncAttributeMaxDynamicSharedMemorySize, 81920);

    proj_hmma<<<dim3(32, 16, 3), 256>>>(x, q, k, v);
    rope_kernel<<<32768, 256>>>(theta);
    attn_kernel<<<dim3(64, 16), 256, 81920>>>();
    outproj_hmma<<<dim3(32, 16), 256>>>(o, out);
}

// round 7
// speedup vs baseline: 2.0765x; 1.7370x over previous
#include <cuda_runtime.h>
#include <cuda_bf16.h>
#include <math.h>
#include <stdint.h>

#define SEQ 4096
#define DM  2048
#define NH  16
#define DQK 128

typedef __nv_bfloat16 bf16;

// ---------------- single 128 MiB aliased heap (proven-safe footprint) -------
// [OFF_PQ] fp32 q-proj [16][4096][128]; after rope: per-row packed bf16 hi|lo
// [OFF_PK] same for k
// [OFF_PV] fp32 v-proj [16][4096][128]; later reused as z fp32 [4096][2048]
// [OFF_VT] vThi [16][128][4096] bf16 (16MiB) + vTlo (16MiB)
__device__ __align__(1024) unsigned char g_heap[134217728];
#define OFF_PQ 0u
#define OFF_PK 33554432u
#define OFF_PV 67108864u
#define OFF_VT 100663296u
#define VT_LO  16777216u

// ---------------- helpers ---------------------------------------------------
__device__ __forceinline__ void mma16816(float* c, const uint32_t* a, const uint32_t* b) {
    asm volatile(
        "mma.sync.aligned.m16n8k16.row.col.f32.bf16.bf16.f32 "
        "{%0,%1,%2,%3}, {%4,%5,%6,%7}, {%8,%9}, {%0,%1,%2,%3};"
        : "+f"(c[0]), "+f"(c[1]), "+f"(c[2]), "+f"(c[3])
        : "r"(a[0]), "r"(a[1]), "r"(a[2]), "r"(a[3]), "r"(b[0]), "r"(b[1]));
}
__device__ __forceinline__ void ldsm4(uint32_t* r, uint32_t a) {
    asm volatile("ldmatrix.sync.aligned.m8n8.x4.shared.b16 {%0,%1,%2,%3}, [%4];"
                 : "=r"(r[0]), "=r"(r[1]), "=r"(r[2]), "=r"(r[3]) : "r"(a));
}
__device__ __forceinline__ uint32_t smem_u32(const void* p) {
    uint32_t a;
    asm("{ .reg .u64 t; cvta.to.shared.u64 t, %1; cvt.u32.u64 %0, t; }"
        : "=r"(a) : "l"(p));
    return a;
}
#define CPA16(dst, src) \
    asm volatile("cp.async.cg.shared.global [%0], [%1], 16;" :: "r"(dst), "l"(src))
#define CPA_COMMIT() asm volatile("cp.async.commit_group;" ::: "memory")
#define CPA_WAIT_ALL() asm volatile("cp.async.wait_all;" ::: "memory")

__device__ __forceinline__ uint32_t pack_split(float a, float b, uint32_t& lopk) {
    bf16 ha = __float2bfloat16(a), hb = __float2bfloat16(b);
    bf16 la = __float2bfloat16(a - __bfloat162float(ha));
    bf16 lb = __float2bfloat16(b - __bfloat162float(hb));
    lopk = (uint32_t)__bfloat16_as_ushort(la) |
           ((uint32_t)__bfloat16_as_ushort(lb) << 16);
    return (uint32_t)__bfloat16_as_ushort(ha) |
           ((uint32_t)__bfloat16_as_ushort(hb) << 16);
}

// ---------------------------------------------------------------------------
// Split-bf16 HMMA GEMM v2 (ldmatrix): C[128,128] = A[128,2048] @ B[2048,128]
// 8 warps (2m x 4n), warp tile 64x32, k-chunk 32, static smem 40960 B.
// smem tiles [128 rows][40 halves pitch] (80 B rows: 16B-aligned, ldsm-safe).
// ---------------------------------------------------------------------------
#define PITU 20   // u32 pitch per row

__device__ __forceinline__ void gemm128f(
    const float* __restrict__ A, int lda,
    const float* __restrict__ B, int ldb,
    float* __restrict__ C, int ldc, float scale)
{
    __shared__ uint32_t sm[4 * 128 * PITU];
    uint32_t* sAh = sm;
    uint32_t* sAl = sm + 128 * PITU;
    uint32_t* sBh = sm + 2 * 128 * PITU;
    uint32_t* sBl = sm + 3 * 128 * PITU;
    const uint32_t sb = smem_u32(sm);

    const int t = threadIdx.x, lane = t & 31, wid = t >> 5;
    const int wm = (wid >> 2) * 64, wn = (wid & 3) * 32;

    const int arow = t >> 1, aseg = t & 1;          // A: 2 thr/row, 16 floats
    const int bkp  = t & 15, bnc = (t >> 4) * 8;    // B: 16 k-pairs x 8 n

    const float* pA  = A + (size_t)arow * lda + aseg * 16;
    const float* pB0 = B + (size_t)(2 * bkp) * ldb + bnc;
    const float* pB1 = pB0 + ldb;

    float acc[4][4][4];
#pragma unroll
    for (int i = 0; i < 4; i++)
#pragma unroll
        for (int j = 0; j < 4; j++)
#pragma unroll
            for (int r = 0; r < 4; r++) acc[i][j][r] = 0.0f;

    float a_f[16], b_f[16];
#pragma unroll
    for (int u = 0; u < 4; u++) {
        float4 v = *(const float4*)(pA + u * 4);
        a_f[u*4+0] = v.x; a_f[u*4+1] = v.y; a_f[u*4+2] = v.z; a_f[u*4+3] = v.w;
    }
#pragma unroll
    for (int u = 0; u < 2; u++) {
        float4 v0 = *(const float4*)(pB0 + u * 4);
        float4 v1 = *(const float4*)(pB1 + u * 4);
        b_f[u*4+0] = v0.x; b_f[u*4+1] = v0.y; b_f[u*4+2] = v0.z; b_f[u*4+3] = v0.w;
        b_f[8+u*4+0] = v1.x; b_f[8+u*4+1] = v1.y; b_f[8+u*4+2] = v1.z; b_f[8+u*4+3] = v1.w;
    }

    for (int kc = 0; kc < 64; kc++) {
        __syncthreads();
#pragma unroll
        for (int u2 = 0; u2 < 8; u2++) {
            uint32_t lo, hi = pack_split(a_f[2*u2], a_f[2*u2+1], lo);
            sAh[arow * PITU + aseg * 8 + u2] = hi;
            sAl[arow * PITU + aseg * 8 + u2] = lo;
        }
#pragma unroll
        for (int n = 0; n < 8; n++) {
            uint32_t lo, hi = pack_split(b_f[n], b_f[8 + n], lo);
            sBh[(bnc + n) * PITU + bkp] = hi;
            sBl[(bnc + n) * PITU + bkp] = lo;
        }
        if (kc < 63) {
            const size_t ao = (size_t)(kc + 1) * 32;
            const size_t bo = (size_t)(kc + 1) * 32 * ldb;
#pragma unroll
            for (int u = 0; u < 4; u++) {
                float4 v = *(const float4*)(pA + ao + u * 4);
                a_f[u*4+0] = v.x; a_f[u*4+1] = v.y; a_f[u*4+2] = v.z; a_f[u*4+3] = v.w;
            }
#pragma unroll
            for (int u = 0; u < 2; u++) {
                float4 v0 = *(const float4*)(pB0 + bo + u * 4);
                float4 v1 = *(const float4*)(pB1 + bo + u * 4);
                b_f[u*4+0] = v0.x; b_f[u*4+1] = v0.y; b_f[u*4+2] = v0.z; b_f[u*4+3] = v0.w;
                b_f[8+u*4+0] = v1.x; b_f[8+u*4+1] = v1.y; b_f[8+u*4+2] = v1.z; b_f[8+u*4+3] = v1.w;
            }
        }
        __syncthreads();

#pragma unroll
        for (int ks = 0; ks < 2; ks++) {
            uint32_t ah[4][4], al[4][4], bh[2][4], bl[2][4];
            const uint32_t abase = sb +
                (wm + (lane & 7) + ((lane >> 3) & 1) * 8) * 80 + ks * 32 + (lane >> 4) * 16;
#pragma unroll
            for (int i = 0; i < 4; i++) {
                ldsm4(ah[i], abase + i * 1280);
                ldsm4(al[i], abase + 10240 + i * 1280);
            }
            const uint32_t bbase = sb + 20480 +
                (wn + (lane & 7) + ((lane >> 4) & 1) * 8) * 80 + ks * 32 + ((lane >> 3) & 1) * 16;
#pragma unroll
            for (int jp = 0; jp < 2; jp++) {
                ldsm4(bh[jp], bbase + jp * 1280);
                ldsm4(bl[jp], bbase + 10240 + jp * 1280);
            }
#pragma unroll
            for (int i = 0; i < 4; i++)
#pragma unroll
                for (int j = 0; j < 4; j++) {
                    const uint32_t* bhp = &bh[j >> 1][(j & 1) * 2];
                    const uint32_t* blp = &bl[j >> 1][(j & 1) * 2];
                    mma16816(acc[i][j], ah[i], bhp);
                    mma16816(acc[i][j], al[i], bhp);
                    mma16816(acc[i][j], ah[i], blp);
                }
        }
    }

    const int g = lane >> 2, qq = lane & 3;
#pragma unroll
    for (int i = 0; i < 4; i++)
#pragma unroll
        for (int j = 0; j < 4; j++) {
            const int row = wm + i * 16 + g;
            const int col = wn + j * 8 + qq * 2;
            float2 lo = make_float2(acc[i][j][0] * scale, acc[i][j][1] * scale);
            float2 hi = make_float2(acc[i][j][2] * scale, acc[i][j][3] * scale);
            *(float2*)(C + (size_t)row * ldc + col)       = lo;
            *(float2*)(C + (size_t)(row + 8) * ldc + col) = hi;
        }
}

__global__ void __launch_bounds__(256) proj_hmma(
    const float* __restrict__ x, const float* __restrict__ q,
    const float* __restrict__ k, const float* __restrict__ v)
{
    const int h = blockIdx.y, w = blockIdx.z;
    const float* W = (w == 0 ? q : (w == 1 ? k : v)) + (size_t)h * DM * DQK;
    float* C = (float*)(g_heap + (w == 0 ? OFF_PQ : w == 1 ? OFF_PK : OFF_PV)) +
               (size_t)h * SEQ * DQK + (size_t)blockIdx.x * 128 * DQK;
    gemm128f(x + (size_t)blockIdx.x * 128 * DM, DM, W, DQK, C, DQK, 1.0f);
}

__global__ void __launch_bounds__(256) outproj_hmma(
    const float* __restrict__ o, float* __restrict__ out)
{
    const float* z = (const float*)(g_heap + OFF_PV);
    gemm128f(z + (size_t)blockIdx.x * 128 * 2048, 2048,
             o + blockIdx.y * 128, 2048,
             out + (size_t)blockIdx.x * 128 * DM + blockIdx.y * 128,
             DM, 4.8828125e-4f);
}

// ---------------------------------------------------------------------------
// RoPE + in-place bf16 hi/lo re-pack. Block = 4 complete rows (race-free).
// Row layout after: [128 hi halves | 128 lo halves] in the row's 512 bytes.
// ---------------------------------------------------------------------------
__global__ void __launch_bounds__(256) rope_pack(const float* __restrict__ theta)
{
    const float tf = theta[0];
    const int s = blockIdx.x * 4 + (threadIdx.x >> 6);
    const int j = threadIdx.x & 63;
    const int h = blockIdx.y;
    char* base = (char*)g_heap + (blockIdx.z ? OFF_PK : OFF_PQ) +
                 ((size_t)(h * 4096 + s)) * 512;
    float* rowp = (float*)base;

    const float x1 = rowp[j];
    const float x2 = rowp[j + 64];
    const float rate = tf * (-(float)j * 0.015625f);
    const float rot  = __fmul_rn((float)s, rate);
    float sv, cv;
    sincosf(rot, &sv, &cv);
    const float y1 = (cv * x1 - sv * x2) / 3.36358566101485845f;
    const float y2 = (sv * x1 + cv * x2) / 3.36358566101485845f;

    __syncthreads();   // all reads in this block's 4 rows complete

    bf16* hp = (bf16*)base;
    bf16 h1 = __float2bfloat16(y1);
    bf16 h2 = __float2bfloat16(y2);
    hp[j]            = h1;
    hp[j + 64]       = h2;
    hp[128 + j]      = __float2bfloat16(y1 - __bfloat162float(h1));
    hp[128 + j + 64] = __float2bfloat16(y2 - __bfloat162float(h2));
}

// ---------------------------------------------------------------------------
// pv fp32 [h][s][v] -> vThi/vTlo bf16 [h][v][s]
// ---------------------------------------------------------------------------
__global__ void __launch_bounds__(256) tspv()
{
    __shared__ float tile[32][33];
    const int h = blockIdx.z;
    const float* pv = (const float*)(g_heap + OFF_PV) + (size_t)h * 4096 * 128;
    bf16* vh = (bf16*)(g_heap + OFF_VT) + (size_t)h * 128 * 4096;
    bf16* vl = (bf16*)(g_heap + OFF_VT + VT_LO) + (size_t)h * 128 * 4096;
    const int tx = threadIdx.x, ty = threadIdx.y;
    const int s0 = blockIdx.x * 32, v0 = blockIdx.y * 32;
#pragma unroll
    for (int i = 0; i < 4; i++)
        tile[ty + 8 * i][tx] = pv[(size_t)(s0 + ty + 8 * i) * 128 + v0 + tx];
    __syncthreads();
#pragma unroll
    for (int i = 0; i < 4; i++) {
        float v = tile[tx][ty + 8 * i];
        bf16 hh = __float2bfloat16(v);
        vh[(size_t)(v0 + ty + 8 * i) * 4096 + s0 + tx] = hh;
        vl[(size_t)(v0 + ty + 8 * i) * 4096 + s0 + tx] =
            __float2bfloat16(v - __bfloat162float(hh));
    }
}

// ---------------------------------------------------------------------------
// Flash attention (HMMA). CTA = (head, 128 q-rows), 8 warps, warp = 16 rows.
// 64-key tiles, cp.async double-buffered K/V from packed/split sources.
// smem: Qh/Ql [128][136h]; per buf: Kh/Kl [64][136h], Vh/Vl [128][72h]. 212992 B.
// ---------------------------------------------------------------------------
#define AQH 0u
#define AQL 34816u
#define ABUF 69632u
#define BUFSZ 71680u
#define BKH 0u
#define BKL 17408u
#define BVH 34816u
#define BVL 53248u

__global__ void __launch_bounds__(256) attn_hmma()
{
    extern __shared__ char smem[];
    const uint32_t sb = smem_u32(smem);
    const int t = threadIdx.x, lane = t & 31, wid = t >> 5;
    const int g = lane >> 2, qq = lane & 3;
    const int bx = blockIdx.x;
    const int qt = 31 - (bx >> 4);     // heavy tiles first
    const int h  = bx & 15;
    const int r0 = qt * 128;
    const int jmax = 2 * qt + 1;

    const char* qbase = (const char*)g_heap + OFF_PQ + ((size_t)(h * 4096 + r0)) * 512;
    const char* kbase = (const char*)g_heap + OFF_PK + ((size_t)h * 4096) * 512;

    // Q (persistent): packed rows -> smem hi/lo, pitch 272 B
    {
        const char* src = qbase + (size_t)(t & 127) * 512 + (t >> 7) * 256;
        const uint32_t dst = sb + ((t >> 7) ? AQL : AQH) + (t & 127) * 272;
#pragma unroll
        for (int u = 0; u < 16; u++) CPA16(dst + u * 16, src + u * 16);
    }
    const int krow = t & 63, kseg = (t >> 6) & 1, kha = t >> 7;
    const int vrow = t & 127, vha = t >> 7;
    const char* vsrc0 = (const char*)g_heap + OFF_VT + (vha ? VT_LO : 0u) +
                        ((size_t)h * 128 + vrow) * 8192;
    // tile 0
    {
        const char* ksrc = kbase + (size_t)krow * 512 + kha * 256 + kseg * 128;
        const uint32_t kdst = sb + ABUF + (kha ? BKL : BKH) + krow * 272 + kseg * 128;
#pragma unroll
        for (int u = 0; u < 8; u++) CPA16(kdst + u * 16, ksrc + u * 16);
        const uint32_t vdst = sb + ABUF + (vha ? BVL : BVH) + vrow * 144;
#pragma unroll
        for (int u = 0; u < 8; u++) CPA16(vdst + u * 16, vsrc0 + u * 16);
    }
    CPA_COMMIT();

    float zacc[16][4];
#pragma unroll
    for (int n = 0; n < 16; n++)
#pragma unroll
        for (int r = 0; r < 4; r++) zacc[n][r] = 0.0f;
    float m0 = -3e38f, m1 = -3e38f, l0 = 0.0f, l1 = 0.0f;

    const uint32_t* sQh = (const uint32_t*)(smem + AQH);
    const uint32_t* sQl = (const uint32_t*)(smem + AQL);

    for (int j = 0; j <= jmax; j++) {
        const int b = j & 1;
        const char* bufc = smem + ABUF + b * BUFSZ;
        CPA_WAIT_ALL();
        __syncthreads();

        if (j < jmax) {
            const int col1 = (j + 1) * 64;
            const uint32_t ob = sb + ABUF + (b ^ 1) * BUFSZ;
            const char* ksrc = kbase + (size_t)(col1 + krow) * 512 + kha * 256 + kseg * 128;
            const uint32_t kdst = ob + (kha ? BKL : BKH) + krow * 272 + kseg * 128;
#pragma unroll
            for (int u = 0; u < 8; u++) CPA16(kdst + u * 16, ksrc + u * 16);
            const char* vsrc = vsrc0 + col1 * 2;
            const uint32_t vdst = ob + (vha ? BVL : BVH) + vrow * 144;
#pragma unroll
            for (int u = 0; u < 8; u++) CPA16(vdst + u * 16, vsrc + u * 16);
            CPA_COMMIT();
        }

        const uint32_t* sKh = (const uint32_t*)(bufc + BKH);
        const uint32_t* sKl = (const uint32_t*)(bufc + BKL);
        const uint32_t* sVh = (const uint32_t*)(bufc + BVH);
        const uint32_t* sVl = (const uint32_t*)(bufc + BVL);

        // ---- S = Q @ K^T : warp m16 x n64 ----
        float sacc[8][4];
#pragma unroll
        for (int n = 0; n < 8; n++)
#pragma unroll
            for (int r = 0; r < 4; r++) sacc[n][r] = 0.0f;

#pragma unroll
        for (int ks = 0; ks < 8; ks++) {
            const int aw = (wid * 16 + g) * 68 + ks * 8 + qq;
            uint32_t qh[4] = { sQh[aw], sQh[aw + 8*68], sQh[aw + 4], sQh[aw + 8*68 + 4] };
            uint32_t ql[4] = { sQl[aw], sQl[aw + 8*68], sQl[aw + 4], sQl[aw + 8*68 + 4] };
#pragma unroll
            for (int n = 0; n < 8; n++) {
                const int bw = (n * 8 + g) * 68 + ks * 8 + qq;
                uint32_t kh[2] = { sKh[bw], sKh[bw + 4] };
                uint32_t kl[2] = { sKl[bw], sKl[bw + 4] };
                mma16816(sacc[n], qh, kh);
                mma16816(sacc[n], ql, kh);
                mma16816(sacc[n], qh, kl);
            }
        }

        // ---- causal mask (only diagonal-overlap tiles) ----
        if (j >= 2 * qt) {
            const int rowlo = r0 + wid * 16 + g;
            const int colb  = j * 64 + qq * 2;
#pragma unroll
            for (int n = 0; n < 8; n++) {
                const int c0 = colb + n * 8, c1 = c0 + 1;
                if (c0 > rowlo)     sacc[n][0] = -1e30f;
                if (c1 > rowlo)     sacc[n][1] = -1e30f;
                if (c0 > rowlo + 8) sacc[n][2] = -1e30f;
                if (c1 > rowlo + 8) sacc[n][3] = -1e30f;
            }
        }

        // ---- online softmax (rows g and g+8; quad reductions) ----
        float rm0 = -3e38f, rm1 = -3e38f;
#pragma unroll
        for (int n = 0; n < 8; n++) {
            rm0 = fmaxf(rm0, fmaxf(sacc[n][0], sacc[n][1]));
            rm1 = fmaxf(rm1, fmaxf(sacc[n][2], sacc[n][3]));
        }
        rm0 = fmaxf(rm0, __shfl_xor_sync(0xffffffffu, rm0, 1));
        rm0 = fmaxf(rm0, __shfl_xor_sync(0xffffffffu, rm0, 2));
        rm1 = fmaxf(rm1, __shfl_xor_sync(0xffffffffu, rm1, 1));
        rm1 = fmaxf(rm1, __shfl_xor_sync(0xffffffffu, rm1, 2));
        const float mn0 = fmaxf(m0, rm0), mn1 = fmaxf(m1, rm1);
        const float al0 = __expf(m0 - mn0), al1 = __expf(m1 - mn1);
        m0 = mn0; m1 = mn1;

        float rs0 = 0.0f, rs1 = 0.0f;
#pragma unroll
        for (int n = 0; n < 8; n++) {
            sacc[n][0] = __expf(sacc[n][0] - mn0);
            sacc[n][1] = __expf(sacc[n][1] - mn0);
            sacc[n][2] = __expf(sacc[n][2] - mn1);
            sacc[n][3] = __expf(sacc[n][3] - mn1);
            rs0 += sacc[n][0] + sacc[n][1];
            rs1 += sacc[n][2] + sacc[n][3];
        }
        rs0 += __shfl_xor_sync(0xffffffffu, rs0, 1);
        rs0 += __shfl_xor_sync(0xffffffffu, rs0, 2);
        rs1 += __shfl_xor_sync(0xffffffffu, rs1, 1);
        rs1 += __shfl_xor_sync(0xffffffffu, rs1, 2);
        l0 = l0 * al0 + rs0;
        l1 = l1 * al1 + rs1;

#pragma unroll
        for (int n = 0; n < 16; n++) {
            zacc[n][0] *= al0; zacc[n][1] *= al0;
            zacc[n][2] *= al1; zacc[n][3] *= al1;
        }

        // ---- pack P as A-fragments ----
        uint32_t pa_h[4][4], pa_l[4][4];
#pragma unroll
        for (int kt = 0; kt < 4; kt++) {
            pa_h[kt][0] = pack_split(sacc[2*kt][0],   sacc[2*kt][1],   pa_l[kt][0]);
            pa_h[kt][1] = pack_split(sacc[2*kt][2],   sacc[2*kt][3],   pa_l[kt][1]);
            pa_h[kt][2] = pack_split(sacc[2*kt+1][0], sacc[2*kt+1][1], pa_l[kt][2]);
            pa_h[kt][3] = pack_split(sacc[2*kt+1][2], sacc[2*kt+1][3], pa_l[kt][3]);
        }

        // ---- Z += P @ V : m16 x n128, k=64 ----
#pragma unroll
        for (int n = 0; n < 16; n++) {
#pragma unroll
            for (int kt = 0; kt < 4; kt++) {
                const int bw = (n * 8 + g) * 36 + kt * 8 + qq;
                uint32_t vh[2] = { sVh[bw], sVh[bw + 4] };
                uint32_t vl[2] = { sVl[bw], sVl[bw + 4] };
                mma16816(zacc[n], pa_h[kt], vh);
                mma16816(zacc[n], pa_l[kt], vh);
                mma16816(zacc[n], pa_h[kt], vl);
            }
        }
        __syncthreads();
    }

    // ---- normalize, write z fp32 [s][h*128+v] ----
    const float i0 = 1.0f / l0, i1 = 1.0f / l1;
    float* zp = (float*)(g_heap + OFF_PV);
    const int rowlo = r0 + wid * 16 + g;
#pragma unroll
    for (int n = 0; n < 16; n++) {
        const int col = h * 128 + n * 8 + qq * 2;
        *(float2*)(zp + (size_t)rowlo * 2048 + col) =
            make_float2(zacc[n][0] * i0, zacc[n][1] * i0);
        *(float2*)(zp + (size_t)(rowlo + 8) * 2048 + col) =
            make_float2(zacc[n][2] * i1, zacc[n][3] * i1);
    }
}

// ---------------------------------------------------------------------------
extern "C" void kernel_launch(void* const* d_in, const int* in_sizes, int n_in,
                              void* d_out, int out_size)
{
    const float* x     = (const float*)d_in[0];
    const float* q     = (const float*)d_in[1];
    const float* k     = (const float*)d_in[2];
    const float* v     = (const float*)d_in[3];
    const float* o     = (const float*)d_in[4];
    const float* theta = (const float*)d_in[5];
    float* out = (float*)d_out;

    cudaFuncSetAttribute(attn_hmma,
                         cudaFuncAttributeMaxDynamicSharedMemorySize, 212992);

    proj_hmma<<<dim3(32, 16, 3), 256>>>(x, q, k, v);
    rope_pack<<<dim3(1024, 16, 2), 256>>>(theta);
    tspv<<<dim3(128, 4, 16), dim3(32, 8)>>>();
    attn_hmma<<<512, 256, 212992>>>();
    outproj_hmma<<<dim3(32, 16), 256>>>(o, out);
}

// round 8
// speedup vs baseline: 2.3076x; 1.1113x over previous
#include <cuda_runtime.h>
#include <cuda_bf16.h>
#include <math.h>
#include <stdint.h>

#define SEQ 4096
#define DM  2048
#define NH  16
#define DQK 128

typedef __nv_bfloat16 bf16;

// ---------------- single 128 MiB aliased heap (proven-safe footprint) -------
__device__ __align__(1024) unsigned char g_heap[134217728];
#define OFF_PQ 0u
#define OFF_PK 33554432u
#define OFF_PV 67108864u
#define OFF_VT 100663296u
#define VT_LO  16777216u

// ---------------- helpers ---------------------------------------------------
__device__ __forceinline__ void mma16816(float* c, const uint32_t* a, const uint32_t* b) {
    asm volatile(
        "mma.sync.aligned.m16n8k16.row.col.f32.bf16.bf16.f32 "
        "{%0,%1,%2,%3}, {%4,%5,%6,%7}, {%8,%9}, {%0,%1,%2,%3};"
        : "+f"(c[0]), "+f"(c[1]), "+f"(c[2]), "+f"(c[3])
        : "r"(a[0]), "r"(a[1]), "r"(a[2]), "r"(a[3]), "r"(b[0]), "r"(b[1]));
}
__device__ __forceinline__ void ldsm4(uint32_t* r, uint32_t a) {
    asm volatile("ldmatrix.sync.aligned.m8n8.x4.shared.b16 {%0,%1,%2,%3}, [%4];"
                 : "=r"(r[0]), "=r"(r[1]), "=r"(r[2]), "=r"(r[3]) : "r"(a));
}
__device__ __forceinline__ uint32_t smem_u32(const void* p) {
    uint32_t a;
    asm("{ .reg .u64 t; cvta.to.shared.u64 t, %1; cvt.u32.u64 %0, t; }"
        : "=r"(a) : "l"(p));
    return a;
}
#define CPA16(dst, src) \
    asm volatile("cp.async.cg.shared.global [%0], [%1], 16;" :: "r"(dst), "l"(src))
#define CPA_COMMIT() asm volatile("cp.async.commit_group;" ::: "memory")
#define CPA_WAIT_ALL() asm volatile("cp.async.wait_all;" ::: "memory")

__device__ __forceinline__ uint32_t pack_split(float a, float b, uint32_t& lopk) {
    bf16 ha = __float2bfloat16(a), hb = __float2bfloat16(b);
    bf16 la = __float2bfloat16(a - __bfloat162float(ha));
    bf16 lb = __float2bfloat16(b - __bfloat162float(hb));
    lopk = (uint32_t)__bfloat16_as_ushort(la) |
           ((uint32_t)__bfloat16_as_ushort(lb) << 16);
    return (uint32_t)__bfloat16_as_ushort(ha) |
           ((uint32_t)__bfloat16_as_ushort(hb) << 16);
}

// ---------------------------------------------------------------------------
// Split-bf16 HMMA GEMM v3: 512 threads, 16 warps (2m x 8n), warp tile 64x16.
// C[128,128] = A[128,2048] @ B[2048,128]   (B is [k][n], n contiguous)
// k-chunk 32; smem 40960 B; ~110 regs/thread -> 16 resident warps.
// smem tiles [128 rows][40 halves pitch = 80 B] (proven ldsm mapping).
// ---------------------------------------------------------------------------
#define PITU 20   // u32 pitch per row

__device__ __forceinline__ void gemm128f(
    const float* __restrict__ A, int lda,
    const float* __restrict__ B, int ldb,
    float* __restrict__ C, int ldc, float scale)
{
    __shared__ uint32_t sm[4 * 128 * PITU];
    uint32_t* sAh = sm;
    uint32_t* sAl = sm + 128 * PITU;
    uint32_t* sBh = sm + 2 * 128 * PITU;
    uint32_t* sBl = sm + 3 * 128 * PITU;
    const uint32_t sb = smem_u32(sm);

    const int t = threadIdx.x, lane = t & 31, wid = t >> 5;
    const int wm = (wid >> 3) * 64, wn = (wid & 7) * 16;

    // loaders (512 threads)
    const int arow = t >> 2, aseg = t & 3;          // A: 4 thr/row, 8 floats each
    const int bkp  = t & 15, bnc = (t >> 4) * 4;    // B: 16 k-pairs x 4 n

    const float* pA  = A + (size_t)arow * lda + aseg * 8;
    const float* pB0 = B + (size_t)(2 * bkp) * ldb + bnc;
    const float* pB1 = pB0 + ldb;

    float acc[4][2][4];
#pragma unroll
    for (int i = 0; i < 4; i++)
#pragma unroll
        for (int j = 0; j < 2; j++)
#pragma unroll
            for (int r = 0; r < 4; r++) acc[i][j][r] = 0.0f;

    float a_f[8], b_f[8];
#pragma unroll
    for (int u = 0; u < 2; u++) {
        float4 v = *(const float4*)(pA + u * 4);
        a_f[u*4+0] = v.x; a_f[u*4+1] = v.y; a_f[u*4+2] = v.z; a_f[u*4+3] = v.w;
    }
    {
        float4 v0 = *(const float4*)pB0;
        float4 v1 = *(const float4*)pB1;
        b_f[0] = v0.x; b_f[1] = v0.y; b_f[2] = v0.z; b_f[3] = v0.w;
        b_f[4] = v1.x; b_f[5] = v1.y; b_f[6] = v1.z; b_f[7] = v1.w;
    }

    for (int kc = 0; kc < 64; kc++) {
        __syncthreads();
#pragma unroll
        for (int u2 = 0; u2 < 4; u2++) {
            uint32_t lo, hi = pack_split(a_f[2*u2], a_f[2*u2+1], lo);
            sAh[arow * PITU + aseg * 4 + u2] = hi;
            sAl[arow * PITU + aseg * 4 + u2] = lo;
        }
#pragma unroll
        for (int n = 0; n < 4; n++) {
            uint32_t lo, hi = pack_split(b_f[n], b_f[4 + n], lo);
            sBh[(bnc + n) * PITU + bkp] = hi;
            sBl[(bnc + n) * PITU + bkp] = lo;
        }
        if (kc < 63) {
            const size_t ao = (size_t)(kc + 1) * 32;
            const size_t bo = (size_t)(kc + 1) * 32 * ldb;
#pragma unroll
            for (int u = 0; u < 2; u++) {
                float4 v = *(const float4*)(pA + ao + u * 4);
                a_f[u*4+0] = v.x; a_f[u*4+1] = v.y; a_f[u*4+2] = v.z; a_f[u*4+3] = v.w;
            }
            {
                float4 v0 = *(const float4*)(pB0 + bo);
                float4 v1 = *(const float4*)(pB1 + bo);
                b_f[0] = v0.x; b_f[1] = v0.y; b_f[2] = v0.z; b_f[3] = v0.w;
                b_f[4] = v1.x; b_f[5] = v1.y; b_f[6] = v1.z; b_f[7] = v1.w;
            }
        }
        __syncthreads();

#pragma unroll
        for (int ks = 0; ks < 2; ks++) {
            uint32_t ah[4][4], al[4][4], bh[4], bl[4];
            const uint32_t abase = sb +
                (wm + (lane & 7) + ((lane >> 3) & 1) * 8) * 80 + ks * 32 + (lane >> 4) * 16;
#pragma unroll
            for (int i = 0; i < 4; i++) {
                ldsm4(ah[i], abase + i * 1280);
                ldsm4(al[i], abase + 10240 + i * 1280);
            }
            const uint32_t bbase = sb + 20480 +
                (wn + (lane & 7) + ((lane >> 4) & 1) * 8) * 80 + ks * 32 + ((lane >> 3) & 1) * 16;
            ldsm4(bh, bbase);
            ldsm4(bl, bbase + 10240);
#pragma unroll
            for (int i = 0; i < 4; i++)
#pragma unroll
                for (int j = 0; j < 2; j++) {
                    mma16816(acc[i][j], ah[i], &bh[j * 2]);
                    mma16816(acc[i][j], al[i], &bh[j * 2]);
                    mma16816(acc[i][j], ah[i], &bl[j * 2]);
                }
        }
    }

    const int g = lane >> 2, qq = lane & 3;
#pragma unroll
    for (int i = 0; i < 4; i++)
#pragma unroll
        for (int j = 0; j < 2; j++) {
            const int row = wm + i * 16 + g;
            const int col = wn + j * 8 + qq * 2;
            float2 lo = make_float2(acc[i][j][0] * scale, acc[i][j][1] * scale);
            float2 hi = make_float2(acc[i][j][2] * scale, acc[i][j][3] * scale);
            *(float2*)(C + (size_t)row * ldc + col)       = lo;
            *(float2*)(C + (size_t)(row + 8) * ldc + col) = hi;
        }
}

__global__ void __launch_bounds__(512) proj_hmma(
    const float* __restrict__ x, const float* __restrict__ q,
    const float* __restrict__ k, const float* __restrict__ v)
{
    const int h = blockIdx.y, w = blockIdx.z;
    const float* W = (w == 0 ? q : (w == 1 ? k : v)) + (size_t)h * DM * DQK;
    float* C = (float*)(g_heap + (w == 0 ? OFF_PQ : w == 1 ? OFF_PK : OFF_PV)) +
               (size_t)h * SEQ * DQK + (size_t)blockIdx.x * 128 * DQK;
    gemm128f(x + (size_t)blockIdx.x * 128 * DM, DM, W, DQK, C, DQK, 1.0f);
}

__global__ void __launch_bounds__(512) outproj_hmma(
    const float* __restrict__ o, float* __restrict__ out)
{
    const float* z = (const float*)(g_heap + OFF_PV);
    gemm128f(z + (size_t)blockIdx.x * 128 * 2048, 2048,
             o + blockIdx.y * 128, 2048,
             out + (size_t)blockIdx.x * 128 * DM + blockIdx.y * 128,
             DM, 4.8828125e-4f);
}

// ---------------------------------------------------------------------------
// RoPE + in-place bf16 hi/lo re-pack (unchanged, proven)
// ---------------------------------------------------------------------------
__global__ void __launch_bounds__(256) rope_pack(const float* __restrict__ theta)
{
    const float tf = theta[0];
    const int s = blockIdx.x * 4 + (threadIdx.x >> 6);
    const int j = threadIdx.x & 63;
    const int h = blockIdx.y;
    char* base = (char*)g_heap + (blockIdx.z ? OFF_PK : OFF_PQ) +
                 ((size_t)(h * 4096 + s)) * 512;
    float* rowp = (float*)base;

    const float x1 = rowp[j];
    const float x2 = rowp[j + 64];
    const float rate = tf * (-(float)j * 0.015625f);
    const float rot  = __fmul_rn((float)s, rate);
    float sv, cv;
    sincosf(rot, &sv, &cv);
    const float y1 = (cv * x1 - sv * x2) / 3.36358566101485845f;
    const float y2 = (sv * x1 + cv * x2) / 3.36358566101485845f;

    __syncthreads();

    bf16* hp = (bf16*)base;
    bf16 h1 = __float2bfloat16(y1);
    bf16 h2 = __float2bfloat16(y2);
    hp[j]            = h1;
    hp[j + 64]       = h2;
    hp[128 + j]      = __float2bfloat16(y1 - __bfloat162float(h1));
    hp[128 + j + 64] = __float2bfloat16(y2 - __bfloat162float(h2));
}

// ---------------------------------------------------------------------------
// pv fp32 [h][s][v] -> vThi/vTlo bf16 [h][v][s]  (unchanged, proven)
// ---------------------------------------------------------------------------
__global__ void __launch_bounds__(256) tspv()
{
    __shared__ float tile[32][33];
    const int h = blockIdx.z;
    const float* pv = (const float*)(g_heap + OFF_PV) + (size_t)h * 4096 * 128;
    bf16* vh = (bf16*)(g_heap + OFF_VT) + (size_t)h * 128 * 4096;
    bf16* vl = (bf16*)(g_heap + OFF_VT + VT_LO) + (size_t)h * 128 * 4096;
    const int tx = threadIdx.x, ty = threadIdx.y;
    const int s0 = blockIdx.x * 32, v0 = blockIdx.y * 32;
#pragma unroll
    for (int i = 0; i < 4; i++)
        tile[ty + 8 * i][tx] = pv[(size_t)(s0 + ty + 8 * i) * 128 + v0 + tx];
    __syncthreads();
#pragma unroll
    for (int i = 0; i < 4; i++) {
        float v = tile[tx][ty + 8 * i];
        bf16 hh = __float2bfloat16(v);
        vh[(size_t)(v0 + ty + 8 * i) * 4096 + s0 + tx] = hh;
        vl[(size_t)(v0 + ty + 8 * i) * 4096 + s0 + tx] =
            __float2bfloat16(v - __bfloat162float(hh));
    }
}

// ---------------------------------------------------------------------------
// Flash attention (HMMA + ldmatrix fragments). Structure identical to R7.
// smem: Qh/Ql [128][136h] (pitch 272 B); per buf: Kh/Kl [64][136h],
//       Vh/Vl [128][72h] (pitch 144 B). Total 212992 B.
// ---------------------------------------------------------------------------
#define AQH 0u
#define AQL 34816u
#define ABUF 69632u
#define BUFSZ 71680u
#define BKH 0u
#define BKL 17408u
#define BVH 34816u
#define BVL 53248u

__global__ void __launch_bounds__(256) attn_hmma()
{
    extern __shared__ char smem[];
    const uint32_t sb = smem_u32(smem);
    const int t = threadIdx.x, lane = t & 31, wid = t >> 5;
    const int g = lane >> 2, qq = lane & 3;
    const int bx = blockIdx.x;
    const int qt = 31 - (bx >> 4);     // heavy tiles first
    const int h  = bx & 15;
    const int r0 = qt * 128;
    const int jmax = 2 * qt + 1;

    const char* qbase = (const char*)g_heap + OFF_PQ + ((size_t)(h * 4096 + r0)) * 512;
    const char* kbase = (const char*)g_heap + OFF_PK + ((size_t)h * 4096) * 512;

    // Q (persistent)
    {
        const char* src = qbase + (size_t)(t & 127) * 512 + (t >> 7) * 256;
        const uint32_t dst = sb + ((t >> 7) ? AQL : AQH) + (t & 127) * 272;
#pragma unroll
        for (int u = 0; u < 16; u++) CPA16(dst + u * 16, src + u * 16);
    }
    const int krow = t & 63, kseg = (t >> 6) & 1, kha = t >> 7;
    const int vrow = t & 127, vha = t >> 7;
    const char* vsrc0 = (const char*)g_heap + OFF_VT + (vha ? VT_LO : 0u) +
                        ((size_t)h * 128 + vrow) * 8192;
    {
        const char* ksrc = kbase + (size_t)krow * 512 + kha * 256 + kseg * 128;
        const uint32_t kdst = sb + ABUF + (kha ? BKL : BKH) + krow * 272 + kseg * 128;
#pragma unroll
        for (int u = 0; u < 8; u++) CPA16(kdst + u * 16, ksrc + u * 16);
        const uint32_t vdst = sb + ABUF + (vha ? BVL : BVH) + vrow * 144;
#pragma unroll
        for (int u = 0; u < 8; u++) CPA16(vdst + u * 16, vsrc0 + u * 16);
    }
    CPA_COMMIT();

    float zacc[16][4];
#pragma unroll
    for (int n = 0; n < 16; n++)
#pragma unroll
        for (int r = 0; r < 4; r++) zacc[n][r] = 0.0f;
    float m0 = -3e38f, m1 = -3e38f, l0 = 0.0f, l1 = 0.0f;

    for (int j = 0; j <= jmax; j++) {
        const int b = j & 1;
        const uint32_t sbuf = sb + ABUF + b * BUFSZ;
        CPA_WAIT_ALL();
        __syncthreads();

        if (j < jmax) {
            const int col1 = (j + 1) * 64;
            const uint32_t ob = sb + ABUF + (b ^ 1) * BUFSZ;
            const char* ksrc = kbase + (size_t)(col1 + krow) * 512 + kha * 256 + kseg * 128;
            const uint32_t kdst = ob + (kha ? BKL : BKH) + krow * 272 + kseg * 128;
#pragma unroll
            for (int u = 0; u < 8; u++) CPA16(kdst + u * 16, ksrc + u * 16);
            const char* vsrc = vsrc0 + col1 * 2;
            const uint32_t vdst = ob + (vha ? BVL : BVH) + vrow * 144;
#pragma unroll
            for (int u = 0; u < 8; u++) CPA16(vdst + u * 16, vsrc + u * 16);
            CPA_COMMIT();
        }

        // ---- S = Q @ K^T : warp m16 x n64 (ldmatrix fragments) ----
        float sacc[8][4];
#pragma unroll
        for (int n = 0; n < 8; n++)
#pragma unroll
            for (int r = 0; r < 4; r++) sacc[n][r] = 0.0f;

#pragma unroll
        for (int ks = 0; ks < 8; ks++) {
            uint32_t qh[4], ql[4];
            const uint32_t qa = sb + AQH +
                (wid * 16 + (lane & 7) + ((lane >> 3) & 1) * 8) * 272 +
                ks * 32 + (lane >> 4) * 16;
            ldsm4(qh, qa);
            ldsm4(ql, qa + 34816);
#pragma unroll
            for (int n2 = 0; n2 < 4; n2++) {
                uint32_t kh[4], kl[4];
                const uint32_t ka = sbuf + BKH +
                    (n2 * 16 + (lane & 7) + ((lane >> 4) & 1) * 8) * 272 +
                    ks * 32 + ((lane >> 3) & 1) * 16;
                ldsm4(kh, ka);
                ldsm4(kl, ka + 17408);
#pragma unroll
                for (int bb = 0; bb < 2; bb++) {
                    const int n = 2 * n2 + bb;
                    mma16816(sacc[n], qh, &kh[bb * 2]);
                    mma16816(sacc[n], ql, &kh[bb * 2]);
                    mma16816(sacc[n], qh, &kl[bb * 2]);
                }
            }
        }

        // ---- causal mask ----
        if (j >= 2 * qt) {
            const int rowlo = r0 + wid * 16 + g;
            const int colb  = j * 64 + qq * 2;
#pragma unroll
            for (int n = 0; n < 8; n++) {
                const int c0 = colb + n * 8, c1 = c0 + 1;
                if (c0 > rowlo)     sacc[n][0] = -1e30f;
                if (c1 > rowlo)     sacc[n][1] = -1e30f;
                if (c0 > rowlo + 8) sacc[n][2] = -1e30f;
                if (c1 > rowlo + 8) sacc[n][3] = -1e30f;
            }
        }

        // ---- online softmax ----
        float rm0 = -3e38f, rm1 = -3e38f;
#pragma unroll
        for (int n = 0; n < 8; n++) {
            rm0 = fmaxf(rm0, fmaxf(sacc[n][0], sacc[n][1]));
            rm1 = fmaxf(rm1, fmaxf(sacc[n][2], sacc[n][3]));
        }
        rm0 = fmaxf(rm0, __shfl_xor_sync(0xffffffffu, rm0, 1));
        rm0 = fmaxf(rm0, __shfl_xor_sync(0xffffffffu, rm0, 2));
        rm1 = fmaxf(rm1, __shfl_xor_sync(0xffffffffu, rm1, 1));
        rm1 = fmaxf(rm1, __shfl_xor_sync(0xffffffffu, rm1, 2));
        const float mn0 = fmaxf(m0, rm0), mn1 = fmaxf(m1, rm1);
        const float al0 = __expf(m0 - mn0), al1 = __expf(m1 - mn1);
        m0 = mn0; m1 = mn1;

        float rs0 = 0.0f, rs1 = 0.0f;
#pragma unroll
        for (int n = 0; n < 8; n++) {
            sacc[n][0] = __expf(sacc[n][0] - mn0);
            sacc[n][1] = __expf(sacc[n][1] - mn0);
            sacc[n][2] = __expf(sacc[n][2] - mn1);
            sacc[n][3] = __expf(sacc[n][3] - mn1);
            rs0 += sacc[n][0] + sacc[n][1];
            rs1 += sacc[n][2] + sacc[n][3];
        }
        rs0 += __shfl_xor_sync(0xffffffffu, rs0, 1);
        rs0 += __shfl_xor_sync(0xffffffffu, rs0, 2);
        rs1 += __shfl_xor_sync(0xffffffffu, rs1, 1);
        rs1 += __shfl_xor_sync(0xffffffffu, rs1, 2);
        l0 = l0 * al0 + rs0;
        l1 = l1 * al1 + rs1;

#pragma unroll
        for (int n = 0; n < 16; n++) {
            zacc[n][0] *= al0; zacc[n][1] *= al0;
            zacc[n][2] *= al1; zacc[n][3] *= al1;
        }

        // ---- pack P as A-fragments ----
        uint32_t pa_h[4][4], pa_l[4][4];
#pragma unroll
        for (int kt = 0; kt < 4; kt++) {
            pa_h[kt][0] = pack_split(sacc[2*kt][0],   sacc[2*kt][1],   pa_l[kt][0]);
            pa_h[kt][1] = pack_split(sacc[2*kt][2],   sacc[2*kt][3],   pa_l[kt][1]);
            pa_h[kt][2] = pack_split(sacc[2*kt+1][0], sacc[2*kt+1][1], pa_l[kt][2]);
            pa_h[kt][3] = pack_split(sacc[2*kt+1][2], sacc[2*kt+1][3], pa_l[kt][3]);
        }

        // ---- Z += P @ V : m16 x n128, k=64 (ldmatrix fragments) ----
#pragma unroll
        for (int kt = 0; kt < 4; kt++) {
#pragma unroll
            for (int n2 = 0; n2 < 8; n2++) {
                uint32_t vh[4], vl[4];
                const uint32_t va = sbuf + BVH +
                    (n2 * 16 + (lane & 7) + ((lane >> 4) & 1) * 8) * 144 +
                    kt * 32 + ((lane >> 3) & 1) * 16;
                ldsm4(vh, va);
                ldsm4(vl, va + 18432);
#pragma unroll
                for (int bb = 0; bb < 2; bb++) {
                    const int n = 2 * n2 + bb;
                    mma16816(zacc[n], pa_h[kt], &vh[bb * 2]);
                    mma16816(zacc[n], pa_l[kt], &vh[bb * 2]);
                    mma16816(zacc[n], pa_h[kt], &vl[bb * 2]);
                }
            }
        }
        __syncthreads();
    }

    // ---- normalize, write z fp32 [s][h*128+v] ----
    const float i0 = 1.0f / l0, i1 = 1.0f / l1;
    float* zp = (float*)(g_heap + OFF_PV);
    const int rowlo = r0 + wid * 16 + g;
#pragma unroll
    for (int n = 0; n < 16; n++) {
        const int col = h * 128 + n * 8 + qq * 2;
        *(float2*)(zp + (size_t)rowlo * 2048 + col) =
            make_float2(zacc[n][0] * i0, zacc[n][1] * i0);
        *(float2*)(zp + (size_t)(rowlo + 8) * 2048 + col) =
            make_float2(zacc[n][2] * i1, zacc[n][3] * i1);
    }
}

// ---------------------------------------------------------------------------
extern "C" void kernel_launch(void* const* d_in, const int* in_sizes, int n_in,
                              void* d_out, int out_size)
{
    const float* x     = (const float*)d_in[0];
    const float* q     = (const float*)d_in[1];
    const float* k     = (const float*)d_in[2];
    const float* v     = (const float*)d_in[3];
    const float* o     = (const float*)d_in[4];
    const float* theta = (const float*)d_in[5];
    float* out = (float*)d_out;

    cudaFuncSetAttribute(attn_hmma,
                         cudaFuncAttributeMaxDynamicSharedMemorySize, 212992);

    proj_hmma<<<dim3(32, 16, 3), 512>>>(x, q, k, v);
    rope_pack<<<dim3(1024, 16, 2), 256>>>(theta);
    tspv<<<dim3(128, 4, 16), dim3(32, 8)>>>();
    attn_hmma<<<512, 256, 212992>>>();
    outproj_hmma<<<dim3(32, 16), 512>>>(o, out);
}

// round 10
// speedup vs baseline: 2.6880x; 1.1648x over previous
#include <cuda_runtime.h>
#include <cuda_bf16.h>
#include <math.h>
#include <stdint.h>

#define SEQ 4096
#define DM  2048
#define NH  16
#define DQK 128

typedef __nv_bfloat16 bf16;

// ---------------- single 128 MiB heap, phase-overlaid (all sizes audited) ---
// [0,32M)    Q fp32 proj -> rope_pack in place -> packed bf16 hi|lo rows
//            after attn: oT split (OTH/OTL, 16M)
// [32,64M)   K same
// [64,96M)   V fp32 proj (PVf) -> after tspv: z fp32 (attn output)
// [96,112M)  W split scratch (8M hi + 8M lo, rewritten per kind)
// [96,128M)  after proj: vT hi [96,112M) + vT lo [112,128M)
__device__ __align__(1024) unsigned char g_heap[134217728];
#define QOFF 0u
#define KOFF 33554432u
#define ZOFF 67108864u
#define WH   100663296u
#define WL   109051904u
#define VTH  100663296u
#define VTL  117440512u
#define OTH  0u
#define OTL  8388608u

// ---------------- helpers ---------------------------------------------------
__device__ __forceinline__ void mma16816(float* c, const uint32_t* a, const uint32_t* b) {
    asm volatile(
        "mma.sync.aligned.m16n8k16.row.col.f32.bf16.bf16.f32 "
        "{%0,%1,%2,%3}, {%4,%5,%6,%7}, {%8,%9}, {%0,%1,%2,%3};"
        : "+f"(c[0]), "+f"(c[1]), "+f"(c[2]), "+f"(c[3])
        : "r"(a[0]), "r"(a[1]), "r"(a[2]), "r"(a[3]), "r"(b[0]), "r"(b[1]));
}
__device__ __forceinline__ void ldsm4(uint32_t* r, uint32_t a) {
    asm volatile("ldmatrix.sync.aligned.m8n8.x4.shared.b16 {%0,%1,%2,%3}, [%4];"
                 : "=r"(r[0]), "=r"(r[1]), "=r"(r[2]), "=r"(r[3]) : "r"(a));
}
__device__ __forceinline__ uint32_t smem_u32(const void* p) {
    uint32_t a;
    asm("{ .reg .u64 t; cvta.to.shared.u64 t, %1; cvt.u32.u64 %0, t; }"
        : "=r"(a) : "l"(p));
    return a;
}
#define CPA16(dst, src) \
    asm volatile("cp.async.cg.shared.global [%0], [%1], 16;" :: "r"(dst), "l"(src))
#define CPA_COMMIT() asm volatile("cp.async.commit_group;" ::: "memory")
#define CPA_WAIT_ALL() asm volatile("cp.async.wait_all;" ::: "memory")
#define CPA_WAIT1() asm volatile("cp.async.wait_group 1;" ::: "memory")

__device__ __forceinline__ uint32_t pack_split(float a, float b, uint32_t& lopk) {
    bf16 ha = __float2bfloat16(a), hb = __float2bfloat16(b);
    bf16 la = __float2bfloat16(a - __bfloat162float(ha));
    bf16 lb = __float2bfloat16(b - __bfloat162float(hb));
    lopk = (uint32_t)__bfloat16_as_ushort(la) |
           ((uint32_t)__bfloat16_as_ushort(lb) << 16);
    return (uint32_t)__bfloat16_as_ushort(ha) |
           ((uint32_t)__bfloat16_as_ushort(hb) << 16);
}

// ---------------------------------------------------------------------------
// GEMM v5: A fp32 (register-prefetch + in-loader split, R8-proven),
//          B pre-split bf16 (cp.async double-buffered).
// C[128,128] = A[128,K] @ (Bh+Bl)[128rows][K]^T, K=2048, k-chunk 32.
// 512 threads, 16 warps (2m x 8n). smem 2 stages x 40960 B.
// Stage layout: Ah +0, Al +10240, Bh +20480, Bl +30720 (80 B row pitch).
// ldsm/mma addressing identical to R8-proven v3.
// ---------------------------------------------------------------------------
__device__ __forceinline__ void gemm_v5(
    const float* __restrict__ A, int lda,
    const bf16* __restrict__ Bh, const bf16* __restrict__ Bl, int ldb,
    float* __restrict__ C, int ldc, float scale)
{
    __shared__ __align__(16) unsigned char sm[81920];
    const uint32_t sb = smem_u32(sm);

    const int t = threadIdx.x, lane = t & 31, wid = t >> 5;
    const int wm = (wid >> 3) * 64, wn = (wid & 7) * 16;

    // A loader: 4 thr/row x 128 rows, 8 floats each
    const int arow = t >> 2, aseg = t & 3;
    const float* pA = A + (size_t)arow * lda + aseg * 8;
    const uint32_t asoff = arow * 80u + aseg * 16u;

    // B loader: 2 tiles (hi/lo) x 128 rows x 2 thr/row (32 B each)
    const int bt = t >> 8, brow = (t >> 1) & 127, bseg = t & 1;
    const char* pB = (const char*)((bt ? Bl : Bh) + (size_t)brow * ldb) + bseg * 32;
    const uint32_t bsoff = 20480u + bt * 10240u + brow * 80u + bseg * 32u;

    float acc[4][2][4];
#pragma unroll
    for (int i = 0; i < 4; i++)
#pragma unroll
        for (int j = 0; j < 2; j++)
#pragma unroll
            for (int r = 0; r < 4; r++) acc[i][j][r] = 0.0f;

    float a_f[8];
    {
        float4 v0 = *(const float4*)pA;
        float4 v1 = *(const float4*)(pA + 4);
        a_f[0] = v0.x; a_f[1] = v0.y; a_f[2] = v0.z; a_f[3] = v0.w;
        a_f[4] = v1.x; a_f[5] = v1.y; a_f[6] = v1.z; a_f[7] = v1.w;
    }
    CPA16(sb + bsoff, pB);
    CPA16(sb + bsoff + 16, pB + 16);
    CPA_COMMIT();

    for (int kc = 0; kc < 64; kc++) {
        const uint32_t st = (kc & 1) * 40960u;
        __syncthreads();   // prior compute done with this stage

        // pack + store A chunk
        {
            uint32_t hi[4], lo[4];
#pragma unroll
            for (int u = 0; u < 4; u++) hi[u] = pack_split(a_f[2*u], a_f[2*u+1], lo[u]);
            *(uint4*)(sm + st + asoff)         = make_uint4(hi[0], hi[1], hi[2], hi[3]);
            *(uint4*)(sm + st + 10240 + asoff) = make_uint4(lo[0], lo[1], lo[2], lo[3]);
        }
        if (kc < 63) {
            const uint32_t ob = ((kc + 1) & 1) * 40960u;
            const char* src = pB + (size_t)(kc + 1) * 64;
            CPA16(sb + ob + bsoff, src);
            CPA16(sb + ob + bsoff + 16, src + 16);
            CPA_COMMIT();
            const float* ap = pA + (size_t)(kc + 1) * 32;
            float4 v0 = *(const float4*)ap;
            float4 v1 = *(const float4*)(ap + 4);
            a_f[0] = v0.x; a_f[1] = v0.y; a_f[2] = v0.z; a_f[3] = v0.w;
            a_f[4] = v1.x; a_f[5] = v1.y; a_f[6] = v1.z; a_f[7] = v1.w;
            CPA_WAIT1();     // current stage's B arrived
        } else {
            CPA_WAIT_ALL();
        }
        __syncthreads();     // A stores + B arrivals visible

#pragma unroll
        for (int ks = 0; ks < 2; ks++) {
            uint32_t ah[4][4], al[4][4], bh4[4], bl4[4];
            const uint32_t abase = sb + st +
                (wm + (lane & 7) + ((lane >> 3) & 1) * 8) * 80 + ks * 32 + (lane >> 4) * 16;
#pragma unroll
            for (int i = 0; i < 4; i++) {
                ldsm4(ah[i], abase + i * 1280);
                ldsm4(al[i], abase + 10240 + i * 1280);
            }
            const uint32_t bbase = sb + st + 20480 +
                (wn + (lane & 7) + ((lane >> 4) & 1) * 8) * 80 + ks * 32 + ((lane >> 3) & 1) * 16;
            ldsm4(bh4, bbase);
            ldsm4(bl4, bbase + 10240);
#pragma unroll
            for (int i = 0; i < 4; i++)
#pragma unroll
                for (int j = 0; j < 2; j++) {
                    mma16816(acc[i][j], ah[i], &bh4[j * 2]);
                    mma16816(acc[i][j], al[i], &bh4[j * 2]);
                    mma16816(acc[i][j], ah[i], &bl4[j * 2]);
                }
        }
    }

    const int g = lane >> 2, qq = lane & 3;
#pragma unroll
    for (int i = 0; i < 4; i++)
#pragma unroll
        for (int j = 0; j < 2; j++) {
            const int row = wm + i * 16 + g;
            const int col = wn + j * 8 + qq * 2;
            float2 lo = make_float2(acc[i][j][0] * scale, acc[i][j][1] * scale);
            float2 hi = make_float2(acc[i][j][2] * scale, acc[i][j][3] * scale);
            *(float2*)(C + (size_t)row * ldc + col)       = lo;
            *(float2*)(C + (size_t)(row + 8) * ldc + col) = hi;
        }
}

__global__ void __launch_bounds__(512) proj_v5(const float* __restrict__ x,
                                              unsigned dstoff)
{
    const int h = blockIdx.y;
    const bf16* bh = (const bf16*)(g_heap + WH) + (size_t)h * 262144;
    const bf16* bl = (const bf16*)(g_heap + WL) + (size_t)h * 262144;
    float* C = (float*)(g_heap + dstoff) +
               (size_t)h * SEQ * DQK + (size_t)blockIdx.x * 128 * DQK;
    gemm_v5(x + (size_t)blockIdx.x * 128 * DM, DM, bh, bl, DM, C, DQK, 1.0f);
}

__global__ void __launch_bounds__(512) outproj_v5(float* __restrict__ out)
{
    const float* z = (const float*)(g_heap + ZOFF);
    const bf16* bh = (const bf16*)(g_heap + OTH) + (size_t)blockIdx.y * 128 * 2048;
    const bf16* bl = (const bf16*)(g_heap + OTL) + (size_t)blockIdx.y * 128 * 2048;
    gemm_v5(z + (size_t)blockIdx.x * 128 * 2048, 2048, bh, bl, 2048,
            out + (size_t)blockIdx.x * 128 * DM + blockIdx.y * 128,
            DM, 4.8828125e-4f);
}

// ---------------------------------------------------------------------------
// prep kernels
// ---------------------------------------------------------------------------
// per-kind: w fp32 [h][k=2048][n=128] -> W scratch bf16 [h][n=128][k=2048]
__global__ void __launch_bounds__(256) splitwT(const float* __restrict__ w)
{
    __shared__ float tile[32][33];
    const int h = blockIdx.z;
    const float* src = w + (size_t)h * 262144;
    bf16* oh = (bf16*)(g_heap + WH) + (size_t)h * 262144;
    bf16* ol = (bf16*)(g_heap + WL) + (size_t)h * 262144;
    const int tx = threadIdx.x, ty = threadIdx.y;
    const int k0 = blockIdx.x * 32, n0 = blockIdx.y * 32;
#pragma unroll
    for (int i = 0; i < 4; i++)
        tile[ty + 8 * i][tx] = src[(size_t)(k0 + ty + 8 * i) * 128 + n0 + tx];
    __syncthreads();
#pragma unroll
    for (int i = 0; i < 4; i++) {
        float v = tile[tx][ty + 8 * i];
        bf16 hh = __float2bfloat16(v);
        oh[(size_t)(n0 + ty + 8 * i) * 2048 + k0 + tx] = hh;
        ol[(size_t)(n0 + ty + 8 * i) * 2048 + k0 + tx] =
            __float2bfloat16(v - __bfloat162float(hh));
    }
}

// o fp32 [a=2048][d=2048] -> oT bf16 [d][a] hi/lo
__global__ void __launch_bounds__(256) osplitT(const float* __restrict__ o)
{
    __shared__ float tile[32][33];
    bf16* oh = (bf16*)(g_heap + OTH);
    bf16* ol = (bf16*)(g_heap + OTL);
    const int tx = threadIdx.x, ty = threadIdx.y;
    const int a0 = blockIdx.x * 32, d0 = blockIdx.y * 32;
#pragma unroll
    for (int i = 0; i < 4; i++)
        tile[ty + 8 * i][tx] = o[(size_t)(a0 + ty + 8 * i) * 2048 + d0 + tx];
    __syncthreads();
#pragma unroll
    for (int i = 0; i < 4; i++) {
        float v = tile[tx][ty + 8 * i];
        bf16 hh = __float2bfloat16(v);
        oh[(size_t)(d0 + ty + 8 * i) * 2048 + a0 + tx] = hh;
        ol[(size_t)(d0 + ty + 8 * i) * 2048 + a0 + tx] =
            __float2bfloat16(v - __bfloat162float(hh));
    }
}

// RoPE + in-place bf16 hi/lo re-pack (R7/R8 proven)
__global__ void __launch_bounds__(256) rope_pack(const float* __restrict__ theta)
{
    const float tf = theta[0];
    const int s = blockIdx.x * 4 + (threadIdx.x >> 6);
    const int j = threadIdx.x & 63;
    const int h = blockIdx.y;
    char* base = (char*)g_heap + (blockIdx.z ? KOFF : QOFF) +
                 ((size_t)(h * 4096 + s)) * 512;
    float* rowp = (float*)base;

    const float x1 = rowp[j];
    const float x2 = rowp[j + 64];
    const float rate = tf * (-(float)j * 0.015625f);
    const float rot  = __fmul_rn((float)s, rate);
    float sv, cv;
    sincosf(rot, &sv, &cv);
    const float y1 = (cv * x1 - sv * x2) / 3.36358566101485845f;
    const float y2 = (sv * x1 + cv * x2) / 3.36358566101485845f;

    __syncthreads();

    bf16* hp = (bf16*)base;
    bf16 h1 = __float2bfloat16(y1);
    bf16 h2 = __float2bfloat16(y2);
    hp[j]            = h1;
    hp[j + 64]       = h2;
    hp[128 + j]      = __float2bfloat16(y1 - __bfloat162float(h1));
    hp[128 + j + 64] = __float2bfloat16(y2 - __bfloat162float(h2));
}

// pv fp32 [h][s][v] -> vT bf16 [h][v][s] hi/lo (R8 proven; new offsets)
__global__ void __launch_bounds__(256) tspv()
{
    __shared__ float tile[32][33];
    const int h = blockIdx.z;
    const float* pv = (const float*)(g_heap + ZOFF) + (size_t)h * 4096 * 128;
    bf16* vh = (bf16*)(g_heap + VTH) + (size_t)h * 128 * 4096;
    bf16* vl = (bf16*)(g_heap + VTL) + (size_t)h * 128 * 4096;
    const int tx = threadIdx.x, ty = threadIdx.y;
    const int s0 = blockIdx.x * 32, v0 = blockIdx.y * 32;
#pragma unroll
    for (int i = 0; i < 4; i++)
        tile[ty + 8 * i][tx] = pv[(size_t)(s0 + ty + 8 * i) * 128 + v0 + tx];
    __syncthreads();
#pragma unroll
    for (int i = 0; i < 4; i++) {
        float v = tile[tx][ty + 8 * i];
        bf16 hh = __float2bfloat16(v);
        vh[(size_t)(v0 + ty + 8 * i) * 4096 + s0 + tx] = hh;
        vl[(size_t)(v0 + ty + 8 * i) * 4096 + s0 + tx] =
            __float2bfloat16(v - __bfloat162float(hh));
    }
}

// ---------------------------------------------------------------------------
// Flash attention (R8-proven core; offsets only)
// ---------------------------------------------------------------------------
#define AQH 0u
#define AQL 34816u
#define ABUF 69632u
#define BUFSZ 71680u
#define BKH 0u
#define BKL 17408u
#define BVH 34816u
#define BVL 53248u

__global__ void __launch_bounds__(256) attn_hmma()
{
    extern __shared__ char smem[];
    const uint32_t sb = smem_u32(smem);
    const int t = threadIdx.x, lane = t & 31, wid = t >> 5;
    const int g = lane >> 2, qq = lane & 3;
    const int bx = blockIdx.x;
    const int qt = 31 - (bx >> 4);
    const int h  = bx & 15;
    const int r0 = qt * 128;
    const int jmax = 2 * qt + 1;

    const char* qbase = (const char*)g_heap + QOFF + ((size_t)(h * 4096 + r0)) * 512;
    const char* kbase = (const char*)g_heap + KOFF + ((size_t)h * 4096) * 512;

    {
        const char* src = qbase + (size_t)(t & 127) * 512 + (t >> 7) * 256;
        const uint32_t dst = sb + ((t >> 7) ? AQL : AQH) + (t & 127) * 272;
#pragma unroll
        for (int u = 0; u < 16; u++) CPA16(dst + u * 16, src + u * 16);
    }
    const int krow = t & 63, kseg = (t >> 6) & 1, kha = t >> 7;
    const int vrow = t & 127, vha = t >> 7;
    const char* vsrc0 = (const char*)g_heap + (vha ? VTL : VTH) +
                        ((size_t)h * 128 + vrow) * 8192;
    {
        const char* ksrc = kbase + (size_t)krow * 512 + kha * 256 + kseg * 128;
        const uint32_t kdst = sb + ABUF + (kha ? BKL : BKH) + krow * 272 + kseg * 128;
#pragma unroll
        for (int u = 0; u < 8; u++) CPA16(kdst + u * 16, ksrc + u * 16);
        const uint32_t vdst = sb + ABUF + (vha ? BVL : BVH) + vrow * 144;
#pragma unroll
        for (int u = 0; u < 8; u++) CPA16(vdst + u * 16, vsrc0 + u * 16);
    }
    CPA_COMMIT();

    float zacc[16][4];
#pragma unroll
    for (int n = 0; n < 16; n++)
#pragma unroll
        for (int r = 0; r < 4; r++) zacc[n][r] = 0.0f;
    float m0 = -3e38f, m1 = -3e38f, l0 = 0.0f, l1 = 0.0f;

    for (int j = 0; j <= jmax; j++) {
        const int b = j & 1;
        const uint32_t sbuf = sb + ABUF + b * BUFSZ;
        CPA_WAIT_ALL();
        __syncthreads();

        if (j < jmax) {
            const int col1 = (j + 1) * 64;
            const uint32_t ob = sb + ABUF + (b ^ 1) * BUFSZ;
            const char* ksrc = kbase + (size_t)(col1 + krow) * 512 + kha * 256 + kseg * 128;
            const uint32_t kdst = ob + (kha ? BKL : BKH) + krow * 272 + kseg * 128;
#pragma unroll
            for (int u = 0; u < 8; u++) CPA16(kdst + u * 16, ksrc + u * 16);
            const char* vsrc = vsrc0 + col1 * 2;
            const uint32_t vdst = ob + (vha ? BVL : BVH) + vrow * 144;
#pragma unroll
            for (int u = 0; u < 8; u++) CPA16(vdst + u * 16, vsrc + u * 16);
            CPA_COMMIT();
        }

        float sacc[8][4];
#pragma unroll
        for (int n = 0; n < 8; n++)
#pragma unroll
            for (int r = 0; r < 4; r++) sacc[n][r] = 0.0f;

#pragma unroll
        for (int ks = 0; ks < 8; ks++) {
            uint32_t qh[4], ql[4];
            const uint32_t qa = sb + AQH +
                (wid * 16 + (lane & 7) + ((lane >> 3) & 1) * 8) * 272 +
                ks * 32 + (lane >> 4) * 16;
            ldsm4(qh, qa);
            ldsm4(ql, qa + 34816);
#pragma unroll
            for (int n2 = 0; n2 < 4; n2++) {
                uint32_t kh[4], kl[4];
                const uint32_t ka = sbuf + BKH +
                    (n2 * 16 + (lane & 7) + ((lane >> 4) & 1) * 8) * 272 +
                    ks * 32 + ((lane >> 3) & 1) * 16;
                ldsm4(kh, ka);
                ldsm4(kl, ka + 17408);
#pragma unroll
                for (int bb = 0; bb < 2; bb++) {
                    const int n = 2 * n2 + bb;
                    mma16816(sacc[n], qh, &kh[bb * 2]);
                    mma16816(sacc[n], ql, &kh[bb * 2]);
                    mma16816(sacc[n], qh, &kl[bb * 2]);
                }
            }
        }

        if (j >= 2 * qt) {
            const int rowlo = r0 + wid * 16 + g;
            const int colb  = j * 64 + qq * 2;
#pragma unroll
            for (int n = 0; n < 8; n++) {
                const int c0 = colb + n * 8, c1 = c0 + 1;
                if (c0 > rowlo)     sacc[n][0] = -1e30f;
                if (c1 > rowlo)     sacc[n][1] = -1e30f;
                if (c0 > rowlo + 8) sacc[n][2] = -1e30f;
                if (c1 > rowlo + 8) sacc[n][3] = -1e30f;
            }
        }

        float rm0 = -3e38f, rm1 = -3e38f;
#pragma unroll
        for (int n = 0; n < 8; n++) {
            rm0 = fmaxf(rm0, fmaxf(sacc[n][0], sacc[n][1]));
            rm1 = fmaxf(rm1, fmaxf(sacc[n][2], sacc[n][3]));
        }
        rm0 = fmaxf(rm0, __shfl_xor_sync(0xffffffffu, rm0, 1));
        rm0 = fmaxf(rm0, __shfl_xor_sync(0xffffffffu, rm0, 2));
        rm1 = fmaxf(rm1, __shfl_xor_sync(0xffffffffu, rm1, 1));
        rm1 = fmaxf(rm1, __shfl_xor_sync(0xffffffffu, rm1, 2));
        const float mn0 = fmaxf(m0, rm0), mn1 = fmaxf(m1, rm1);
        const float al0 = __expf(m0 - mn0), al1 = __expf(m1 - mn1);
        m0 = mn0; m1 = mn1;

        float rs0 = 0.0f, rs1 = 0.0f;
#pragma unroll
        for (int n = 0; n < 8; n++) {
            sacc[n][0] = __expf(sacc[n][0] - mn0);
            sacc[n][1] = __expf(sacc[n][1] - mn0);
            sacc[n][2] = __expf(sacc[n][2] - mn1);
            sacc[n][3] = __expf(sacc[n][3] - mn1);
            rs0 += sacc[n][0] + sacc[n][1];
            rs1 += sacc[n][2] + sacc[n][3];
        }
        rs0 += __shfl_xor_sync(0xffffffffu, rs0, 1);
        rs0 += __shfl_xor_sync(0xffffffffu, rs0, 2);
        rs1 += __shfl_xor_sync(0xffffffffu, rs1, 1);
        rs1 += __shfl_xor_sync(0xffffffffu, rs1, 2);
        l0 = l0 * al0 + rs0;
        l1 = l1 * al1 + rs1;

#pragma unroll
        for (int n = 0; n < 16; n++) {
            zacc[n][0] *= al0; zacc[n][1] *= al0;
            zacc[n][2] *= al1; zacc[n][3] *= al1;
        }

        uint32_t pa_h[4][4], pa_l[4][4];
#pragma unroll
        for (int kt = 0; kt < 4; kt++) {
            pa_h[kt][0] = pack_split(sacc[2*kt][0],   sacc[2*kt][1],   pa_l[kt][0]);
            pa_h[kt][1] = pack_split(sacc[2*kt][2],   sacc[2*kt][3],   pa_l[kt][1]);
            pa_h[kt][2] = pack_split(sacc[2*kt+1][0], sacc[2*kt+1][1], pa_l[kt][2]);
            pa_h[kt][3] = pack_split(sacc[2*kt+1][2], sacc[2*kt+1][3], pa_l[kt][3]);
        }

#pragma unroll
        for (int kt = 0; kt < 4; kt++) {
#pragma unroll
            for (int n2 = 0; n2 < 8; n2++) {
                uint32_t vh[4], vl[4];
                const uint32_t va = sbuf + BVH +
                    (n2 * 16 + (lane & 7) + ((lane >> 4) & 1) * 8) * 144 +
                    kt * 32 + ((lane >> 3) & 1) * 16;
                ldsm4(vh, va);
                ldsm4(vl, va + 18432);
#pragma unroll
                for (int bb = 0; bb < 2; bb++) {
                    const int n = 2 * n2 + bb;
                    mma16816(zacc[n], pa_h[kt], &vh[bb * 2]);
                    mma16816(zacc[n], pa_l[kt], &vh[bb * 2]);
                    mma16816(zacc[n], pa_h[kt], &vl[bb * 2]);
                }
            }
        }
        __syncthreads();
    }

    // normalize, write z fp32 [s][h*128+v]
    const float i0 = 1.0f / l0, i1 = 1.0f / l1;
    float* zp = (float*)(g_heap + ZOFF);
    const int rowlo = r0 + wid * 16 + g;
#pragma unroll
    for (int n = 0; n < 16; n++) {
        const int col = h * 128 + n * 8 + qq * 2;
        *(float2*)(zp + (size_t)rowlo * 2048 + col) =
            make_float2(zacc[n][0] * i0, zacc[n][1] * i0);
        *(float2*)(zp + (size_t)(rowlo + 8) * 2048 + col) =
            make_float2(zacc[n][2] * i1, zacc[n][3] * i1);
    }
}

// ---------------------------------------------------------------------------
extern "C" void kernel_launch(void* const* d_in, const int* in_sizes, int n_in,
                              void* d_out, int out_size)
{
    const float* x     = (const float*)d_in[0];
    const float* q     = (const float*)d_in[1];
    const float* k     = (const float*)d_in[2];
    const float* v     = (const float*)d_in[3];
    const float* o     = (const float*)d_in[4];
    const float* theta = (const float*)d_in[5];
    float* out = (float*)d_out;

    cudaFuncSetAttribute(attn_hmma,
                         cudaFuncAttributeMaxDynamicSharedMemorySize, 212992);

    splitwT<<<dim3(64, 4, 16), dim3(32, 8)>>>(q);
    proj_v5<<<dim3(32, 16), 512>>>(x, QOFF);
    splitwT<<<dim3(64, 4, 16), dim3(32, 8)>>>(k);
    proj_v5<<<dim3(32, 16), 512>>>(x, KOFF);
    splitwT<<<dim3(64, 4, 16), dim3(32, 8)>>>(v);
    proj_v5<<<dim3(32, 16), 512>>>(x, ZOFF);
    rope_pack<<<dim3(1024, 16, 2), 256>>>(theta);
    tspv<<<dim3(128, 4, 16), dim3(32, 8)>>>();
    attn_hmma<<<512, 256, 212992>>>();
    osplitT<<<dim3(64, 64), dim3(32, 8)>>>(o);
    outproj_v5<<<dim3(32, 16), 512>>>(out);
}